// round 8
// baseline (speedup 1.0000x reference)
#include <cuda_runtime.h>
#include <cuda_fp16.h>
#include <math.h>

// Problem-shape constants (N=50000, E=1600000, D=64, H=2)
#define NN 50000
#define EE 1600000
#define DD 64
#define HDIM 128   // H*D

#define SCAN_BLOCKS 49   // ceil(50000/1024)

// ---------------- scratch (device globals; no allocation allowed) ----------
__device__ float    g_adot_i[NN * 2];   // <h[n,h,:], att_i[h]>  (via x-space dots)
__device__ float    g_adot_j[NN * 2];
__device__ float    g_s[NN * 2];        // segment sum of exp(alpha) over src
__device__ float    g_sinv[NN * 2];     // 0.5/(s+1e-16)
__device__ float    g_ebdot[30];        // <bond_emb[f,v,h,:], att_j[h]>
__device__ float    g_u[4 * DD];        // [ui_h0, ui_h1, uj_h0, uj_h1] 64-vecs
__device__ float    g_c[4];             // ci0, ci1, cj0, cj1 (bW dot att)
__device__ unsigned g_bsumh[125 * DD];  // half2 per (code,d): (bond'[h0,d], bond'[h1,d])
__device__ int      g_cnt[NN];          // in-degree (by col/dst)
__device__ int      g_base[NN];         // exclusive scan
__device__ int      g_cursor[NN];       // atomic cursors
__device__ int      g_part[64];         // scan partials
__device__ float4   g_rec[EE];          // sorted-by-dst: {row|code<<17, e0, e1, 0}
__device__ float    g_z[NN * HDIM];     // weighted x sums  [n][h*64+d]

__device__ __forceinline__ void red_add_v2(float* p, float a, float b) {
    asm volatile("red.global.add.v2.f32 [%0], {%1,%2};"
                 :: "l"(p), "f"(a), "f"(b) : "memory");
}

// ---------------- K0: zero s / cnt ------------------------------------------
__global__ void k_init(int N) {
    int i = blockIdx.x * blockDim.x + threadIdx.x;
    if (i < N * 2) g_s[i] = 0.0f;
    if (i < N) g_cnt[i] = 0;
}

// ---------------- K1: precompute tables -------------------------------------
__global__ void k_prep(const float* __restrict__ W, const float* __restrict__ bW,
                       const float* __restrict__ att, const float* __restrict__ bond_emb) {
    int bid = blockIdx.x;
    int t = threadIdx.x;
    if (bid < 125) {
        if (t < DD) {   // d = t; pack (h0,h1) halves + fold bW
            int a0 = bid / 25, a1 = (bid / 5) % 5, a2 = bid % 5;
            float v0 = bond_emb[(0 * 5 + a0) * HDIM + t]
                     + bond_emb[(1 * 5 + a1) * HDIM + t]
                     + bond_emb[(2 * 5 + a2) * HDIM + t] + bW[t];
            float v1 = bond_emb[(0 * 5 + a0) * HDIM + DD + t]
                     + bond_emb[(1 * 5 + a1) * HDIM + DD + t]
                     + bond_emb[(2 * 5 + a2) * HDIM + DD + t] + bW[DD + t];
            __half2 hv = __float22half2_rn(make_float2(v0, v1));
            g_bsumh[bid * DD + t] = *reinterpret_cast<unsigned*>(&hv);
        }
        return;
    }
    // block 125
    if (t < 128) {       // u vectors: (hh, d)
        int hh = t >> 6, d = t & 63;
        const float* wr = W + d * HDIM + hh * DD;
        const float* ai = att + hh * HDIM;
        const float* aj = att + hh * HDIM + DD;
        float ui = 0.f, uj = 0.f;
        #pragma unroll 8
        for (int k = 0; k < DD; k++) { ui += wr[k] * ai[k]; uj += wr[k] * aj[k]; }
        g_u[hh * DD + d] = ui;
        g_u[128 + hh * DD + d] = uj;
    } else if (t < 158) {  // ebdot
        int idx = t - 128;
        int f = idx / 10, v = (idx / 2) % 5, hh = idx & 1;
        const float* emb = bond_emb + (f * 5 + v) * HDIM + hh * DD;
        const float* aj  = att + hh * HDIM + DD;
        float acc = 0.0f;
        #pragma unroll 8
        for (int d = 0; d < DD; d++) acc += emb[d] * aj[d];
        g_ebdot[idx] = acc;
    } else if (t == 158) { // bW consts
        for (int hh = 0; hh < 2; hh++) {
            float ci = 0.f, cj = 0.f;
            for (int d = 0; d < DD; d++) {
                float b = bW[hh * DD + d];
                ci += b * att[hh * HDIM + d];
                cj += b * att[hh * HDIM + DD + d];
            }
            g_c[hh] = ci;
            g_c[2 + hh] = cj;
        }
    }
}

// ---------------- K2: per-node attention dots (x-space) + dst histogram ----
__global__ void __launch_bounds__(256) k_adot_hist(const float* __restrict__ x,
                                                   const int* __restrict__ ei,
                                                   int N, int E) {
    __shared__ float su[256];
    int t = threadIdx.x;
    su[t] = g_u[t];
    __syncthreads();

    int e = blockIdx.x * 256 + t;
    if (e < E) atomicAdd(&g_cnt[ei[E + e]], 1);

    int lane = t & 31;
    int n = blockIdx.x * 8 + (t >> 5);
    if (n >= N) return;
    float2 xv = reinterpret_cast<const float2*>(x)[n * 32 + lane];  // d=2lane,2lane+1
    float ai0 = xv.x * su[2 * lane]          + xv.y * su[2 * lane + 1];
    float ai1 = xv.x * su[64 + 2 * lane]     + xv.y * su[64 + 2 * lane + 1];
    float aj0 = xv.x * su[128 + 2 * lane]    + xv.y * su[128 + 2 * lane + 1];
    float aj1 = xv.x * su[192 + 2 * lane]    + xv.y * su[192 + 2 * lane + 1];
    #pragma unroll
    for (int o = 16; o > 0; o >>= 1) {
        ai0 += __shfl_down_sync(0xffffffffu, ai0, o);
        ai1 += __shfl_down_sync(0xffffffffu, ai1, o);
        aj0 += __shfl_down_sync(0xffffffffu, aj0, o);
        aj1 += __shfl_down_sync(0xffffffffu, aj1, o);
    }
    if (lane == 0) {
        reinterpret_cast<float2*>(g_adot_i)[n] = make_float2(ai0 + g_c[0], ai1 + g_c[1]);
        reinterpret_cast<float2*>(g_adot_j)[n] = make_float2(aj0 + g_c[2], aj1 + g_c[3]);
    }
}

// ---------------- K3: 3-phase coalesced scan of cnt -------------------------
// Phase 1: per-block sums (coalesced)
__global__ void __launch_bounds__(1024) k_scan1(int N) {
    __shared__ int sred[32];
    int t = threadIdx.x;
    int i = blockIdx.x * 1024 + t;
    int v = (i < N) ? g_cnt[i] : 0;
    int s = v;
    #pragma unroll
    for (int o = 16; o > 0; o >>= 1) s += __shfl_down_sync(0xffffffffu, s, o);
    if ((t & 31) == 0) sred[t >> 5] = s;
    __syncthreads();
    if (t < 32) {
        int r = sred[t];
        #pragma unroll
        for (int o = 16; o > 0; o >>= 1) r += __shfl_down_sync(0xffffffffu, r, o);
        if (t == 0) g_part[blockIdx.x] = r;
    }
}

// Phase 2: exclusive scan of block partials (one tiny block)
__global__ void k_scan2() {
    __shared__ int sp[64];
    int t = threadIdx.x;  // 64 threads
    int v = (t < SCAN_BLOCKS) ? g_part[t] : 0;
    sp[t] = v;
    __syncthreads();
    #pragma unroll
    for (int off = 1; off < 64; off <<= 1) {
        int u = (t >= off) ? sp[t - off] : 0;
        __syncthreads();
        sp[t] += u;
        __syncthreads();
    }
    if (t < SCAN_BLOCKS) g_part[t] = sp[t] - v;   // exclusive
}

// Phase 3: per-block inclusive scan + offset; write base & cursor (coalesced)
__global__ void __launch_bounds__(1024) k_scan3(int N) {
    __shared__ int ss[1024];
    int t = threadIdx.x;
    int i = blockIdx.x * 1024 + t;
    int v = (i < N) ? g_cnt[i] : 0;
    ss[t] = v;
    __syncthreads();
    #pragma unroll
    for (int off = 1; off < 1024; off <<= 1) {
        int u = (t >= off) ? ss[t - off] : 0;
        __syncthreads();
        ss[t] += u;
        __syncthreads();
    }
    if (i < N) {
        int excl = ss[t] - v + g_part[blockIdx.x];
        g_base[i] = excl;
        g_cursor[i] = excl;
    }
}

// ---------------- K4: fused logits+leakyrelu+exp+segsum+perm ---------------
__global__ void k_softperm(const int* __restrict__ ei, const int* __restrict__ eattr, int E) {
    __shared__ float seb[30];
    if (threadIdx.x < 30) seb[threadIdx.x] = g_ebdot[threadIdx.x];
    __syncthreads();
    int e = blockIdx.x * blockDim.x + threadIdx.x;
    if (e >= E) return;
    int row = ei[e];
    int col = ei[E + e];
    int a0 = eattr[e * 3 + 0], a1 = eattr[e * 3 + 1], a2 = eattr[e * 3 + 2];
    float2 di = reinterpret_cast<const float2*>(g_adot_i)[col];
    float2 dj = reinterpret_cast<const float2*>(g_adot_j)[row];
    float al0 = di.x + dj.x + seb[a0 * 2]     + seb[10 + a1 * 2]     + seb[20 + a2 * 2];
    float al1 = di.y + dj.y + seb[a0 * 2 + 1] + seb[10 + a1 * 2 + 1] + seb[20 + a2 * 2 + 1];
    al0 = (al0 >= 0.f) ? al0 : 0.2f * al0;
    al1 = (al1 >= 0.f) ? al1 : 0.2f * al1;
    float e0 = __expf(al0);
    float e1 = __expf(al1);
    red_add_v2(&g_s[row * 2], e0, e1);
    int code = a0 * 25 + a1 * 5 + a2;
    int packed = row | (code << 17);
    int pos = atomicAdd(&g_cursor[col], 1);
    g_rec[pos] = make_float4(__int_as_float(packed), e0, e1, 0.f);
}

// ---------------- K5: sinv = 0.5/(s+eps) ------------------------------------
__global__ void k_sinv(int N) {
    int i = blockIdx.x * blockDim.x + threadIdx.x;
    if (i < N * 2) g_sinv[i] = __fdividef(0.5f, g_s[i] + 1e-16f);
}

// ---------------- K6: per-dst aggregation of x (no atomics) -----------------
#define AGGR_BODY(KK)                                                              \
    {                                                                              \
        int pk = __shfl_sync(0xffffffffu, pkl, KK);                                \
        float w0 = __shfl_sync(0xffffffffu, w0l, KK);                              \
        float w1 = __shfl_sync(0xffffffffu, w1l, KK);                              \
        int row = pk & 0x1FFFF;                                                    \
        int code = pk >> 17;                                                       \
        float xa = __ldg(x + row * DD + lane);                                     \
        float xb = __ldg(x + row * DD + 32 + lane);                                \
        z0a += w0 * xa; z1a += w1 * xa;                                            \
        z0b += w0 * xb; z1b += w1 * xb;                                            \
        unsigned ua = sb[code * DD + lane];                                        \
        unsigned ub = sb[code * DD + 32 + lane];                                   \
        float2 fa = __half22float2(*reinterpret_cast<__half2*>(&ua));              \
        float2 fb = __half22float2(*reinterpret_cast<__half2*>(&ub));              \
        ba += w0 * fa.x + w1 * fa.y;                                               \
        bb += w0 * fb.x + w1 * fb.y;                                               \
    }

__global__ void __launch_bounds__(256) k_aggr(const float* __restrict__ x,
                                              float* __restrict__ out, int N) {
    __shared__ unsigned sb[125 * DD];   // 32000 B
    int t = threadIdx.x;
    for (int i = t; i < 125 * DD; i += 256) sb[i] = g_bsumh[i];
    __syncthreads();

    int lane = t & 31;
    int gw = blockIdx.x * 8 + (t >> 5);
    int nw = gridDim.x * 8;

    for (int n = gw; n < N; n += nw) {
        int beg = g_base[n];
        int deg = g_cnt[n];
        float z0a = 0.f, z0b = 0.f, z1a = 0.f, z1b = 0.f, ba = 0.f, bb = 0.f;
        for (int k0 = 0; k0 < deg; k0 += 32) {
            int nb = min(32, deg - k0);
            float4 r = make_float4(0.f, 0.f, 0.f, 0.f);
            float2 si = make_float2(0.f, 0.f);
            int pkl = 0;
            if (lane < nb) {
                r = g_rec[beg + k0 + lane];
                pkl = __float_as_int(r.x);
                si = reinterpret_cast<const float2*>(g_sinv)[pkl & 0x1FFFF];
            }
            float w0l = r.y * si.x;
            float w1l = r.z * si.y;
            if (nb == 32) {
                #pragma unroll 8
                for (int k = 0; k < 32; k++) AGGR_BODY(k)
            } else {
                for (int k = 0; k < nb; k++) AGGR_BODY(k)
            }
        }
        g_z[n * HDIM + lane]      = z0a;
        g_z[n * HDIM + 32 + lane] = z0b;
        g_z[n * HDIM + 64 + lane] = z1a;
        g_z[n * HDIM + 96 + lane] = z1b;
        out[n * DD + lane]      = ba;    // bond part; zgemm adds the rest
        out[n * DD + 32 + lane] = bb;
    }
}

// ---------------- K7: out += z @ W (head-structured) + bias ----------------
__global__ void __launch_bounds__(128) k_zgemm(const float* __restrict__ W,
                                               const float* __restrict__ bias,
                                               float* __restrict__ out, int N) {
    __shared__ float4 sz[16 * 32];      // 16 nodes x 128 floats
    __shared__ float sp[16][128];
    int t = threadIdx.x;
    int hh = t >> 6, dp = t & 63;
    float wcol[DD];
    #pragma unroll
    for (int d = 0; d < DD; d++) wcol[d] = W[d * HDIM + hh * DD + dp];

    int n0 = blockIdx.x * 16;
    for (int i = t; i < 16 * 32; i += 128) {
        int node = n0 + (i >> 5);
        sz[i] = (node < N) ? reinterpret_cast<const float4*>(g_z)[node * 32 + (i & 31)]
                           : make_float4(0.f, 0.f, 0.f, 0.f);
    }
    __syncthreads();

    #pragma unroll 2
    for (int i = 0; i < 16; i++) {
        const float4* zr = sz + i * 32 + hh * 16;
        float acc = 0.f;
        #pragma unroll
        for (int d4 = 0; d4 < 16; d4++) {
            float4 zv = zr[d4];
            acc += zv.x * wcol[d4 * 4 + 0];
            acc += zv.y * wcol[d4 * 4 + 1];
            acc += zv.z * wcol[d4 * 4 + 2];
            acc += zv.w * wcol[d4 * 4 + 3];
        }
        sp[i][t] = acc;
    }
    __syncthreads();

    #pragma unroll
    for (int rep = 0; rep < 8; rep++) {
        int o = rep * 128 + t;            // 0..1023
        int i = o >> 6, dpp = o & 63;
        int node = n0 + i;
        if (node < N) {
            int idx = node * DD + dpp;
            out[idx] = out[idx] + sp[i][dpp] + sp[i][64 + dpp] + bias[dpp];
        }
    }
}

// ---------------- launch ----------------------------------------------------
extern "C" void kernel_launch(void* const* d_in, const int* in_sizes, int n_in,
                              void* d_out, int out_size) {
    const float* x        = (const float*)d_in[0];
    const int*   ei       = (const int*)  d_in[1];
    const int*   eattr    = (const int*)  d_in[2];
    const float* W        = (const float*)d_in[3];
    const float* bW       = (const float*)d_in[4];
    const float* att      = (const float*)d_in[5];
    const float* bias     = (const float*)d_in[6];
    const float* bond_emb = (const float*)d_in[7];
    float* out = (float*)d_out;

    int N = in_sizes[0] / DD;
    int E = in_sizes[1] / 2;

    k_init<<<(N * 2 + 255) / 256, 256>>>(N);
    k_prep<<<126, 256>>>(W, bW, att, bond_emb);
    k_adot_hist<<<(E + 255) / 256, 256>>>(x, ei, N, E);
    k_scan1<<<SCAN_BLOCKS, 1024>>>(N);
    k_scan2<<<1, 64>>>();
    k_scan3<<<SCAN_BLOCKS, 1024>>>(N);
    k_softperm<<<(E + 255) / 256, 256>>>(ei, eattr, E);
    k_sinv<<<(N * 2 + 255) / 256, 256>>>(N);
    k_aggr<<<888, 256>>>(x, out, N);
    k_zgemm<<<(N + 15) / 16, 128>>>(W, bias, out, N);
}

// round 9
// speedup vs baseline: 1.0445x; 1.0445x over previous
#include <cuda_runtime.h>
#include <cuda_fp16.h>
#include <math.h>

// Problem-shape constants (N=50000, E=1600000, D=64, H=2)
#define NN 50000
#define EE 1600000
#define DD 64
#define HDIM 128   // H*D

#define SCAN_BLOCKS 49       // ceil(50000/1024)
#define INIT_BLOCKS 391      // ceil(50000*2/256)

// ---------------- scratch (device globals; no allocation allowed) ----------
__device__ float    g_adot_i[NN * 2];   // <h[n,h,:], att_i[h]>  (x-space dots)
__device__ float    g_adot_j[NN * 2];
__device__ float    g_s[NN * 2];        // segment sum of exp(alpha) over src
__device__ float    g_sinv[NN * 2];     // 0.5/(s+1e-16)
__device__ float    g_ebdot[30];        // <bond_emb[f,v,h,:], att_j[h]>
__device__ float    g_u[4 * DD];        // [ui_h0, ui_h1, uj_h0, uj_h1] 64-vecs
__device__ float    g_c[4];             // ci0, ci1, cj0, cj1 (bW dot att)
__device__ unsigned g_bsumh[125 * DD];  // half2 per (code,d): (bond'[h0,d], bond'[h1,d])
__device__ int      g_cnt[NN];          // in-degree (by col/dst)
__device__ int      g_base[NN];         // exclusive scan
__device__ int      g_cursor[NN];       // atomic cursors
__device__ int      g_part[64];         // scan partials
__device__ float4   g_rec[EE];          // sorted-by-dst: {row|code<<17, e0, e1, 0}
__device__ float    g_z[NN * HDIM];     // weighted x sums  [n][h*64+d]

__device__ __forceinline__ void red_add_v2(float* p, float a, float b) {
    asm volatile("red.global.add.v2.f32 [%0], {%1,%2};"
                 :: "l"(p), "f"(a), "f"(b) : "memory");
}

// ---------------- K0: init (zero s/cnt) + precompute tables, fused ---------
__global__ void k_initprep(const float* __restrict__ W, const float* __restrict__ bW,
                           const float* __restrict__ att, const float* __restrict__ bond_emb,
                           int N) {
    int bid = blockIdx.x;
    int t = threadIdx.x;
    if (bid < INIT_BLOCKS) {            // zero s / cnt
        int i = bid * 256 + t;
        if (i < N * 2) g_s[i] = 0.0f;
        if (i < N) g_cnt[i] = 0;
        return;
    }
    bid -= INIT_BLOCKS;                 // 0..125
    if (bid < 125) {
        if (t < DD) {   // d = t; pack (h0,h1) halves + fold bW
            int a0 = bid / 25, a1 = (bid / 5) % 5, a2 = bid % 5;
            float v0 = bond_emb[(0 * 5 + a0) * HDIM + t]
                     + bond_emb[(1 * 5 + a1) * HDIM + t]
                     + bond_emb[(2 * 5 + a2) * HDIM + t] + bW[t];
            float v1 = bond_emb[(0 * 5 + a0) * HDIM + DD + t]
                     + bond_emb[(1 * 5 + a1) * HDIM + DD + t]
                     + bond_emb[(2 * 5 + a2) * HDIM + DD + t] + bW[DD + t];
            __half2 hv = __float22half2_rn(make_float2(v0, v1));
            g_bsumh[bid * DD + t] = *reinterpret_cast<unsigned*>(&hv);
        }
        return;
    }
    // last block: u vectors, ebdot, c consts
    if (t < 128) {       // u vectors: (hh, d)
        int hh = t >> 6, d = t & 63;
        const float* wr = W + d * HDIM + hh * DD;
        const float* ai = att + hh * HDIM;
        const float* aj = att + hh * HDIM + DD;
        float ui = 0.f, uj = 0.f;
        #pragma unroll 8
        for (int k = 0; k < DD; k++) { ui += wr[k] * ai[k]; uj += wr[k] * aj[k]; }
        g_u[hh * DD + d] = ui;
        g_u[128 + hh * DD + d] = uj;
    } else if (t < 158) {  // ebdot
        int idx = t - 128;
        int f = idx / 10, v = (idx / 2) % 5, hh = idx & 1;
        const float* emb = bond_emb + (f * 5 + v) * HDIM + hh * DD;
        const float* aj  = att + hh * HDIM + DD;
        float acc = 0.0f;
        #pragma unroll 8
        for (int d = 0; d < DD; d++) acc += emb[d] * aj[d];
        g_ebdot[idx] = acc;
    } else if (t == 158) { // bW consts
        for (int hh = 0; hh < 2; hh++) {
            float ci = 0.f, cj = 0.f;
            for (int d = 0; d < DD; d++) {
                float b = bW[hh * DD + d];
                ci += b * att[hh * HDIM + d];
                cj += b * att[hh * HDIM + DD + d];
            }
            g_c[hh] = ci;
            g_c[2 + hh] = cj;
        }
    }
}

// ---------------- K1: per-node attention dots (x-space) + dst histogram ----
__global__ void __launch_bounds__(256) k_adot_hist(const float* __restrict__ x,
                                                   const int* __restrict__ ei,
                                                   int N, int E) {
    __shared__ float su[256];
    int t = threadIdx.x;
    su[t] = g_u[t];
    __syncthreads();

    int e = blockIdx.x * 256 + t;
    if (e < E) atomicAdd(&g_cnt[ei[E + e]], 1);

    int lane = t & 31;
    int n = blockIdx.x * 8 + (t >> 5);
    if (n >= N) return;
    float2 xv = reinterpret_cast<const float2*>(x)[n * 32 + lane];  // d=2lane,2lane+1
    float ai0 = xv.x * su[2 * lane]          + xv.y * su[2 * lane + 1];
    float ai1 = xv.x * su[64 + 2 * lane]     + xv.y * su[64 + 2 * lane + 1];
    float aj0 = xv.x * su[128 + 2 * lane]    + xv.y * su[128 + 2 * lane + 1];
    float aj1 = xv.x * su[192 + 2 * lane]    + xv.y * su[192 + 2 * lane + 1];
    #pragma unroll
    for (int o = 16; o > 0; o >>= 1) {
        ai0 += __shfl_down_sync(0xffffffffu, ai0, o);
        ai1 += __shfl_down_sync(0xffffffffu, ai1, o);
        aj0 += __shfl_down_sync(0xffffffffu, aj0, o);
        aj1 += __shfl_down_sync(0xffffffffu, aj1, o);
    }
    if (lane == 0) {
        reinterpret_cast<float2*>(g_adot_i)[n] = make_float2(ai0 + g_c[0], ai1 + g_c[1]);
        reinterpret_cast<float2*>(g_adot_j)[n] = make_float2(aj0 + g_c[2], aj1 + g_c[3]);
    }
}

// ---------------- K2: scan phase 1: per-block sums (coalesced) --------------
__global__ void __launch_bounds__(1024) k_scan1(int N) {
    __shared__ int sred[32];
    int t = threadIdx.x;
    int i = blockIdx.x * 1024 + t;
    int v = (i < N) ? g_cnt[i] : 0;
    int s = v;
    #pragma unroll
    for (int o = 16; o > 0; o >>= 1) s += __shfl_down_sync(0xffffffffu, s, o);
    if ((t & 31) == 0) sred[t >> 5] = s;
    __syncthreads();
    if (t < 32) {
        int r = sred[t];
        #pragma unroll
        for (int o = 16; o > 0; o >>= 1) r += __shfl_down_sync(0xffffffffu, r, o);
        if (t == 0) g_part[blockIdx.x] = r;
    }
}

// ---------------- K3: scan phase 2: per-block scan + local offset ----------
// Each block computes its own offset = sum of partials below it (warp reduce).
__global__ void __launch_bounds__(1024) k_scan3(int N) {
    __shared__ int ss[1024];
    __shared__ int soff;
    int t = threadIdx.x;
    int bid = blockIdx.x;
    if (t < 32) {
        int v = 0;
        if (t < bid) v += g_part[t];
        if (t + 32 < bid && t + 32 < SCAN_BLOCKS) v += g_part[t + 32];
        #pragma unroll
        for (int o = 16; o > 0; o >>= 1) v += __shfl_down_sync(0xffffffffu, v, o);
        if (t == 0) soff = v;
    }
    int i = bid * 1024 + t;
    int v = (i < N) ? g_cnt[i] : 0;
    ss[t] = v;
    __syncthreads();
    #pragma unroll
    for (int off = 1; off < 1024; off <<= 1) {
        int u = (t >= off) ? ss[t - off] : 0;
        __syncthreads();
        ss[t] += u;
        __syncthreads();
    }
    if (i < N) {
        int excl = ss[t] - v + soff;
        g_base[i] = excl;
        g_cursor[i] = excl;
    }
}

// ---------------- K4: fused logits+leakyrelu+exp+segsum+perm ---------------
__global__ void k_softperm(const int* __restrict__ ei, const int* __restrict__ eattr, int E) {
    __shared__ float seb[30];
    if (threadIdx.x < 30) seb[threadIdx.x] = g_ebdot[threadIdx.x];
    __syncthreads();
    int e = blockIdx.x * blockDim.x + threadIdx.x;
    if (e >= E) return;
    int row = ei[e];
    int col = ei[E + e];
    int a0 = eattr[e * 3 + 0], a1 = eattr[e * 3 + 1], a2 = eattr[e * 3 + 2];
    float2 di = reinterpret_cast<const float2*>(g_adot_i)[col];
    float2 dj = reinterpret_cast<const float2*>(g_adot_j)[row];
    float al0 = di.x + dj.x + seb[a0 * 2]     + seb[10 + a1 * 2]     + seb[20 + a2 * 2];
    float al1 = di.y + dj.y + seb[a0 * 2 + 1] + seb[10 + a1 * 2 + 1] + seb[20 + a2 * 2 + 1];
    al0 = (al0 >= 0.f) ? al0 : 0.2f * al0;
    al1 = (al1 >= 0.f) ? al1 : 0.2f * al1;
    float e0 = __expf(al0);
    float e1 = __expf(al1);
    red_add_v2(&g_s[row * 2], e0, e1);
    int code = a0 * 25 + a1 * 5 + a2;
    int packed = row | (code << 17);
    int pos = atomicAdd(&g_cursor[col], 1);
    g_rec[pos] = make_float4(__int_as_float(packed), e0, e1, 0.f);
}

// ---------------- K5: sinv = 0.5/(s+eps) ------------------------------------
__global__ void k_sinv(int N) {
    int i = blockIdx.x * blockDim.x + threadIdx.x;
    if (i < N * 2) g_sinv[i] = __fdividef(0.5f, g_s[i] + 1e-16f);
}

// ---------------- K6: per-dst aggregation of x (no atomics) -----------------
// Warp per dst node. Lane owns dims {2lane, 2lane+1}: x gather is one LDG.64,
// bond table one LDS.64 (uint2 of half2), stores are STG.64. z layout stays
// linear [n][h*64+d] for k_zgemm.
#define AGGR_BODY(KK)                                                              \
    {                                                                              \
        int pk = __shfl_sync(0xffffffffu, pkl, KK);                                \
        float w0 = __shfl_sync(0xffffffffu, w0l, KK);                              \
        float w1 = __shfl_sync(0xffffffffu, w1l, KK);                              \
        int row = pk & 0x1FFFF;                                                    \
        int code = pk >> 17;                                                       \
        float2 xv = __ldg(reinterpret_cast<const float2*>(x) + row * 32 + lane);   \
        uint2 u = *reinterpret_cast<const uint2*>(&sb[code * DD + 2 * lane]);      \
        float2 fa = __half22float2(*reinterpret_cast<__half2*>(&u.x));             \
        float2 fb = __half22float2(*reinterpret_cast<__half2*>(&u.y));             \
        z0x += w0 * xv.x; z0y += w0 * xv.y;                                        \
        z1x += w1 * xv.x; z1y += w1 * xv.y;                                        \
        bx += w0 * fa.x + w1 * fa.y;                                               \
        by += w0 * fb.x + w1 * fb.y;                                               \
    }

__global__ void __launch_bounds__(256) k_aggr(const float* __restrict__ x,
                                              float* __restrict__ out, int N) {
    __shared__ unsigned sb[125 * DD];   // 32000 B
    int t = threadIdx.x;
    for (int i = t; i < 125 * DD; i += 256) sb[i] = g_bsumh[i];
    __syncthreads();

    int lane = t & 31;
    int gw = blockIdx.x * 8 + (t >> 5);
    int nw = gridDim.x * 8;

    for (int n = gw; n < N; n += nw) {
        int beg = g_base[n];
        int deg = g_cnt[n];
        float z0x = 0.f, z0y = 0.f, z1x = 0.f, z1y = 0.f, bx = 0.f, by = 0.f;
        for (int k0 = 0; k0 < deg; k0 += 32) {
            int nb = min(32, deg - k0);
            float4 r = make_float4(0.f, 0.f, 0.f, 0.f);
            float2 si = make_float2(0.f, 0.f);
            int pkl = 0;
            if (lane < nb) {
                r = g_rec[beg + k0 + lane];
                pkl = __float_as_int(r.x);
                si = reinterpret_cast<const float2*>(g_sinv)[pkl & 0x1FFFF];
            }
            float w0l = r.y * si.x;
            float w1l = r.z * si.y;
            if (nb == 32) {
                #pragma unroll 8
                for (int k = 0; k < 32; k++) AGGR_BODY(k)
            } else {
                for (int k = 0; k < nb; k++) AGGR_BODY(k)
            }
        }
        float2* zp = reinterpret_cast<float2*>(g_z + n * HDIM);
        zp[lane]      = make_float2(z0x, z0y);   // head0 dims 2lane,2lane+1
        zp[32 + lane] = make_float2(z1x, z1y);   // head1
        reinterpret_cast<float2*>(out)[n * 32 + lane] = make_float2(bx, by);
    }
}

// ---------------- K7: out += z @ W (head-structured) + bias ----------------
__global__ void __launch_bounds__(128) k_zgemm(const float* __restrict__ W,
                                               const float* __restrict__ bias,
                                               float* __restrict__ out, int N) {
    __shared__ float4 sz[16 * 32];      // 16 nodes x 128 floats
    __shared__ float sp[16][128];
    int t = threadIdx.x;
    int hh = t >> 6, dp = t & 63;
    float wcol[DD];
    #pragma unroll
    for (int d = 0; d < DD; d++) wcol[d] = W[d * HDIM + hh * DD + dp];

    int n0 = blockIdx.x * 16;
    for (int i = t; i < 16 * 32; i += 128) {
        int node = n0 + (i >> 5);
        sz[i] = (node < N) ? reinterpret_cast<const float4*>(g_z)[node * 32 + (i & 31)]
                           : make_float4(0.f, 0.f, 0.f, 0.f);
    }
    __syncthreads();

    #pragma unroll 2
    for (int i = 0; i < 16; i++) {
        const float4* zr = sz + i * 32 + hh * 16;
        float acc = 0.f;
        #pragma unroll
        for (int d4 = 0; d4 < 16; d4++) {
            float4 zv = zr[d4];
            acc += zv.x * wcol[d4 * 4 + 0];
            acc += zv.y * wcol[d4 * 4 + 1];
            acc += zv.z * wcol[d4 * 4 + 2];
            acc += zv.w * wcol[d4 * 4 + 3];
        }
        sp[i][t] = acc;
    }
    __syncthreads();

    #pragma unroll
    for (int rep = 0; rep < 8; rep++) {
        int o = rep * 128 + t;            // 0..1023
        int i = o >> 6, dpp = o & 63;
        int node = n0 + i;
        if (node < N) {
            int idx = node * DD + dpp;
            out[idx] = out[idx] + sp[i][dpp] + sp[i][64 + dpp] + bias[dpp];
        }
    }
}

// ---------------- launch ----------------------------------------------------
extern "C" void kernel_launch(void* const* d_in, const int* in_sizes, int n_in,
                              void* d_out, int out_size) {
    const float* x        = (const float*)d_in[0];
    const int*   ei       = (const int*)  d_in[1];
    const int*   eattr    = (const int*)  d_in[2];
    const float* W        = (const float*)d_in[3];
    const float* bW       = (const float*)d_in[4];
    const float* att      = (const float*)d_in[5];
    const float* bias     = (const float*)d_in[6];
    const float* bond_emb = (const float*)d_in[7];
    float* out = (float*)d_out;

    int N = in_sizes[0] / DD;
    int E = in_sizes[1] / 2;

    k_initprep<<<INIT_BLOCKS + 126, 256>>>(W, bW, att, bond_emb, N);
    k_adot_hist<<<(E + 255) / 256, 256>>>(x, ei, N, E);
    k_scan1<<<SCAN_BLOCKS, 1024>>>(N);
    k_scan3<<<SCAN_BLOCKS, 1024>>>(N);
    k_softperm<<<(E + 255) / 256, 256>>>(ei, eattr, E);
    k_sinv<<<(N * 2 + 255) / 256, 256>>>(N);
    k_aggr<<<888, 256>>>(x, out, N);
    k_zgemm<<<(N + 15) / 16, 128>>>(W, bias, out, N);
}

// round 10
// speedup vs baseline: 1.0463x; 1.0017x over previous
#include <cuda_runtime.h>
#include <cuda_fp16.h>
#include <math.h>

// Problem-shape constants (N=50000, E=1600000, D=64, H=2)
#define NN 50000
#define EE 1600000
#define DD 64
#define HDIM 128   // H*D

#define SCAN_BLOCKS 49       // ceil(50000/1024)
#define INIT_BLOCKS 391      // ceil(50000*2/256)

// ---------------- scratch (device globals; no allocation allowed) ----------
__device__ float    g_adot_i[NN * 2];   // <h[n,h,:], att_i[h]>  (x-space dots)
__device__ float    g_adot_j[NN * 2];
__device__ float    g_s[NN * 2];        // segment sum of exp(alpha) over src
__device__ float    g_sinv[NN * 2];     // 0.5/(s+1e-16)
__device__ float    g_ebdot[30];        // <bond_emb[f,v,h,:], att_j[h]>
__device__ float    g_u[4 * DD];        // [ui_h0, ui_h1, uj_h0, uj_h1] 64-vecs
__device__ float    g_c[4];             // ci0, ci1, cj0, cj1 (bW dot att)
__device__ unsigned g_bsumh[125 * DD];  // half2 per (code,d): (bond'[h0,d], bond'[h1,d])
__device__ int      g_cnt[NN];          // in-degree (by col/dst)
__device__ int      g_base[NN];         // exclusive scan
__device__ int      g_cursor[NN];       // atomic cursors
__device__ int      g_part[64];         // scan partials
__device__ float4   g_rec[EE];          // sorted-by-dst: {row|code<<17, e0, e1, 0}
__device__ float    g_z[NN * HDIM];     // weighted x sums  [n][h*64+d]

__device__ __forceinline__ void red_add_v2(float* p, float a, float b) {
    asm volatile("red.global.add.v2.f32 [%0], {%1,%2};"
                 :: "l"(p), "f"(a), "f"(b) : "memory");
}

// ---------------- K0: init (zero s/cnt) + precompute tables, fused ---------
__global__ void k_initprep(const float* __restrict__ W, const float* __restrict__ bW,
                           const float* __restrict__ att, const float* __restrict__ bond_emb,
                           int N) {
    int bid = blockIdx.x;
    int t = threadIdx.x;
    if (bid < INIT_BLOCKS) {            // zero s / cnt
        int i = bid * 256 + t;
        if (i < N * 2) g_s[i] = 0.0f;
        if (i < N) g_cnt[i] = 0;
        return;
    }
    bid -= INIT_BLOCKS;                 // 0..125
    if (bid < 125) {
        if (t < DD) {   // d = t; pack (h0,h1) halves + fold bW
            int a0 = bid / 25, a1 = (bid / 5) % 5, a2 = bid % 5;
            float v0 = bond_emb[(0 * 5 + a0) * HDIM + t]
                     + bond_emb[(1 * 5 + a1) * HDIM + t]
                     + bond_emb[(2 * 5 + a2) * HDIM + t] + bW[t];
            float v1 = bond_emb[(0 * 5 + a0) * HDIM + DD + t]
                     + bond_emb[(1 * 5 + a1) * HDIM + DD + t]
                     + bond_emb[(2 * 5 + a2) * HDIM + DD + t] + bW[DD + t];
            __half2 hv = __float22half2_rn(make_float2(v0, v1));
            g_bsumh[bid * DD + t] = *reinterpret_cast<unsigned*>(&hv);
        }
        return;
    }
    // last block: u vectors, ebdot, c consts
    if (t < 128) {       // u vectors: (hh, d)
        int hh = t >> 6, d = t & 63;
        const float* wr = W + d * HDIM + hh * DD;
        const float* ai = att + hh * HDIM;
        const float* aj = att + hh * HDIM + DD;
        float ui = 0.f, uj = 0.f;
        #pragma unroll 8
        for (int k = 0; k < DD; k++) { ui += wr[k] * ai[k]; uj += wr[k] * aj[k]; }
        g_u[hh * DD + d] = ui;
        g_u[128 + hh * DD + d] = uj;
    } else if (t < 158) {  // ebdot
        int idx = t - 128;
        int f = idx / 10, v = (idx / 2) % 5, hh = idx & 1;
        const float* emb = bond_emb + (f * 5 + v) * HDIM + hh * DD;
        const float* aj  = att + hh * HDIM + DD;
        float acc = 0.0f;
        #pragma unroll 8
        for (int d = 0; d < DD; d++) acc += emb[d] * aj[d];
        g_ebdot[idx] = acc;
    } else if (t == 158) { // bW consts
        for (int hh = 0; hh < 2; hh++) {
            float ci = 0.f, cj = 0.f;
            for (int d = 0; d < DD; d++) {
                float b = bW[hh * DD + d];
                ci += b * att[hh * HDIM + d];
                cj += b * att[hh * HDIM + DD + d];
            }
            g_c[hh] = ci;
            g_c[2 + hh] = cj;
        }
    }
}

// ---------------- K1: per-node attention dots (x-space) + dst histogram ----
__global__ void __launch_bounds__(256) k_adot_hist(const float* __restrict__ x,
                                                   const int* __restrict__ ei,
                                                   int N, int E) {
    __shared__ float su[256];
    int t = threadIdx.x;
    su[t] = g_u[t];
    __syncthreads();

    int e = blockIdx.x * 256 + t;
    if (e < E) atomicAdd(&g_cnt[ei[E + e]], 1);

    int lane = t & 31;
    int n = blockIdx.x * 8 + (t >> 5);
    if (n >= N) return;
    float2 xv = reinterpret_cast<const float2*>(x)[n * 32 + lane];  // d=2lane,2lane+1
    float ai0 = xv.x * su[2 * lane]          + xv.y * su[2 * lane + 1];
    float ai1 = xv.x * su[64 + 2 * lane]     + xv.y * su[64 + 2 * lane + 1];
    float aj0 = xv.x * su[128 + 2 * lane]    + xv.y * su[128 + 2 * lane + 1];
    float aj1 = xv.x * su[192 + 2 * lane]    + xv.y * su[192 + 2 * lane + 1];
    #pragma unroll
    for (int o = 16; o > 0; o >>= 1) {
        ai0 += __shfl_down_sync(0xffffffffu, ai0, o);
        ai1 += __shfl_down_sync(0xffffffffu, ai1, o);
        aj0 += __shfl_down_sync(0xffffffffu, aj0, o);
        aj1 += __shfl_down_sync(0xffffffffu, aj1, o);
    }
    if (lane == 0) {
        reinterpret_cast<float2*>(g_adot_i)[n] = make_float2(ai0 + g_c[0], ai1 + g_c[1]);
        reinterpret_cast<float2*>(g_adot_j)[n] = make_float2(aj0 + g_c[2], aj1 + g_c[3]);
    }
}

// ---------------- K2: scan phase 1: per-block sums (coalesced) --------------
__global__ void __launch_bounds__(1024) k_scan1(int N) {
    __shared__ int sred[32];
    int t = threadIdx.x;
    int i = blockIdx.x * 1024 + t;
    int v = (i < N) ? g_cnt[i] : 0;
    int s = v;
    #pragma unroll
    for (int o = 16; o > 0; o >>= 1) s += __shfl_down_sync(0xffffffffu, s, o);
    if ((t & 31) == 0) sred[t >> 5] = s;
    __syncthreads();
    if (t < 32) {
        int r = sred[t];
        #pragma unroll
        for (int o = 16; o > 0; o >>= 1) r += __shfl_down_sync(0xffffffffu, r, o);
        if (t == 0) g_part[blockIdx.x] = r;
    }
}

// ---------------- K3: scan phase 2: per-block scan + local offset ----------
__global__ void __launch_bounds__(1024) k_scan3(int N) {
    __shared__ int ss[1024];
    __shared__ int soff;
    int t = threadIdx.x;
    int bid = blockIdx.x;
    if (t < 32) {
        int v = 0;
        if (t < bid) v += g_part[t];
        if (t + 32 < bid && t + 32 < SCAN_BLOCKS) v += g_part[t + 32];
        #pragma unroll
        for (int o = 16; o > 0; o >>= 1) v += __shfl_down_sync(0xffffffffu, v, o);
        if (t == 0) soff = v;
    }
    int i = bid * 1024 + t;
    int v = (i < N) ? g_cnt[i] : 0;
    ss[t] = v;
    __syncthreads();
    #pragma unroll
    for (int off = 1; off < 1024; off <<= 1) {
        int u = (t >= off) ? ss[t - off] : 0;
        __syncthreads();
        ss[t] += u;
        __syncthreads();
    }
    if (i < N) {
        int excl = ss[t] - v + soff;
        g_base[i] = excl;
        g_cursor[i] = excl;
    }
}

// ---------------- K4: fused logits+leakyrelu+exp+segsum+perm ---------------
__global__ void k_softperm(const int* __restrict__ ei, const int* __restrict__ eattr, int E) {
    __shared__ float seb[30];
    if (threadIdx.x < 30) seb[threadIdx.x] = g_ebdot[threadIdx.x];
    __syncthreads();
    int e = blockIdx.x * blockDim.x + threadIdx.x;
    if (e >= E) return;
    int row = ei[e];
    int col = ei[E + e];
    int a0 = eattr[e * 3 + 0], a1 = eattr[e * 3 + 1], a2 = eattr[e * 3 + 2];
    float2 di = reinterpret_cast<const float2*>(g_adot_i)[col];
    float2 dj = reinterpret_cast<const float2*>(g_adot_j)[row];
    float al0 = di.x + dj.x + seb[a0 * 2]     + seb[10 + a1 * 2]     + seb[20 + a2 * 2];
    float al1 = di.y + dj.y + seb[a0 * 2 + 1] + seb[10 + a1 * 2 + 1] + seb[20 + a2 * 2 + 1];
    al0 = (al0 >= 0.f) ? al0 : 0.2f * al0;
    al1 = (al1 >= 0.f) ? al1 : 0.2f * al1;
    float e0 = __expf(al0);
    float e1 = __expf(al1);
    red_add_v2(&g_s[row * 2], e0, e1);
    int code = a0 * 25 + a1 * 5 + a2;
    int packed = row | (code << 17);
    int pos = atomicAdd(&g_cursor[col], 1);
    g_rec[pos] = make_float4(__int_as_float(packed), e0, e1, 0.f);
}

// ---------------- K5: sinv = 0.5/(s+eps) ------------------------------------
__global__ void k_sinv(int N) {
    int i = blockIdx.x * blockDim.x + threadIdx.x;
    if (i < N * 2) g_sinv[i] = __fdividef(0.5f, g_s[i] + 1e-16f);
}

// ---------------- K6: per-dst aggregation of x (no atomics) -----------------
// Warp per dst node; HALF-WARP per edge with float4 lanes (j=lane&15 owns dims
// 4j..4j+3). Records staged in smem and consumed via LDS.128 broadcast (no
// shfl). Halves accumulate alternating edges; combined via shfl_xor(16) at
// node end. Per-edge LSU ops: 0.5 LDG.128(x) + 0.5 LDS.128(bond) + 0.5
// LDS.128(record) vs previous ~3.
#define AGGR_PAIR(KK)                                                              \
    {                                                                              \
        float4 rr = st[warp][2 * (KK) + sub];                                      \
        int pk = __float_as_int(rr.x);                                             \
        float w0 = rr.y, w1 = rr.z;                                                \
        int row = pk & 0x1FFFF;                                                    \
        int code = pk >> 17;                                                       \
        float4 xv = __ldg(reinterpret_cast<const float4*>(x) + row * 16 + j);      \
        uint4 u = *reinterpret_cast<const uint4*>(&sb[code * DD + 4 * j]);         \
        float2 f0 = __half22float2(*reinterpret_cast<__half2*>(&u.x));             \
        float2 f1 = __half22float2(*reinterpret_cast<__half2*>(&u.y));             \
        float2 f2 = __half22float2(*reinterpret_cast<__half2*>(&u.z));             \
        float2 f3 = __half22float2(*reinterpret_cast<__half2*>(&u.w));             \
        z0.x += w0 * xv.x; z0.y += w0 * xv.y; z0.z += w0 * xv.z; z0.w += w0 * xv.w;\
        z1.x += w1 * xv.x; z1.y += w1 * xv.y; z1.z += w1 * xv.z; z1.w += w1 * xv.w;\
        bb.x += w0 * f0.x + w1 * f0.y;                                             \
        bb.y += w0 * f1.x + w1 * f1.y;                                             \
        bb.z += w0 * f2.x + w1 * f2.y;                                             \
        bb.w += w0 * f3.x + w1 * f3.y;                                             \
    }

__global__ void __launch_bounds__(256) k_aggr(const float* __restrict__ x,
                                              float* __restrict__ out, int N) {
    __shared__ unsigned sb[125 * DD];   // 32000 B
    __shared__ float4 st[8][32];        // record staging, 4096 B
    int t = threadIdx.x;
    for (int i = t; i < 125 * DD; i += 256) sb[i] = g_bsumh[i];
    __syncthreads();

    int warp = t >> 5, lane = t & 31;
    int sub = lane >> 4;      // which edge of the pair
    int j = lane & 15;        // float4 lane (dims 4j..4j+3)
    int gw = blockIdx.x * 8 + warp;
    int nw = gridDim.x * 8;

    for (int n = gw; n < N; n += nw) {
        int beg = g_base[n];
        int deg = g_cnt[n];
        float4 z0 = make_float4(0.f, 0.f, 0.f, 0.f);
        float4 z1 = make_float4(0.f, 0.f, 0.f, 0.f);
        float4 bb = make_float4(0.f, 0.f, 0.f, 0.f);
        for (int k0 = 0; k0 < deg; k0 += 32) {
            int nb = min(32, deg - k0);
            float4 sv = make_float4(0.f, 0.f, 0.f, 0.f);   // w=0 padding is inert
            if (lane < nb) {
                float4 r = g_rec[beg + k0 + lane];
                int pk = __float_as_int(r.x);
                float2 si = reinterpret_cast<const float2*>(g_sinv)[pk & 0x1FFFF];
                sv = make_float4(r.x, r.y * si.x, r.z * si.y, 0.f);
            }
            st[warp][lane] = sv;
            __syncwarp();
            if (nb == 32) {
                #pragma unroll
                for (int k = 0; k < 16; k++) AGGR_PAIR(k)
            } else {
                int np = (nb + 1) >> 1;
                for (int k = 0; k < np; k++) AGGR_PAIR(k)
            }
            __syncwarp();
        }
        // combine the two half-warp partials (lanes j and j+16 own same dims)
        z0.x += __shfl_xor_sync(0xffffffffu, z0.x, 16);
        z0.y += __shfl_xor_sync(0xffffffffu, z0.y, 16);
        z0.z += __shfl_xor_sync(0xffffffffu, z0.z, 16);
        z0.w += __shfl_xor_sync(0xffffffffu, z0.w, 16);
        z1.x += __shfl_xor_sync(0xffffffffu, z1.x, 16);
        z1.y += __shfl_xor_sync(0xffffffffu, z1.y, 16);
        z1.z += __shfl_xor_sync(0xffffffffu, z1.z, 16);
        z1.w += __shfl_xor_sync(0xffffffffu, z1.w, 16);
        bb.x += __shfl_xor_sync(0xffffffffu, bb.x, 16);
        bb.y += __shfl_xor_sync(0xffffffffu, bb.y, 16);
        bb.z += __shfl_xor_sync(0xffffffffu, bb.z, 16);
        bb.w += __shfl_xor_sync(0xffffffffu, bb.w, 16);
        if (sub == 0) {
            float4* zp = reinterpret_cast<float4*>(g_z + n * HDIM);
            zp[j]      = z0;   // head0 dims 4j..4j+3
            zp[16 + j] = z1;   // head1
            reinterpret_cast<float4*>(out)[n * 16 + j] = bb;
        }
    }
}

// ---------------- K7: out += z @ W (head-structured) + bias ----------------
__global__ void __launch_bounds__(128) k_zgemm(const float* __restrict__ W,
                                               const float* __restrict__ bias,
                                               float* __restrict__ out, int N) {
    __shared__ float4 sz[16 * 32];      // 16 nodes x 128 floats
    __shared__ float sp[16][128];
    int t = threadIdx.x;
    int hh = t >> 6, dp = t & 63;
    float wcol[DD];
    #pragma unroll
    for (int d = 0; d < DD; d++) wcol[d] = W[d * HDIM + hh * DD + dp];

    int n0 = blockIdx.x * 16;
    for (int i = t; i < 16 * 32; i += 128) {
        int node = n0 + (i >> 5);
        sz[i] = (node < N) ? reinterpret_cast<const float4*>(g_z)[node * 32 + (i & 31)]
                           : make_float4(0.f, 0.f, 0.f, 0.f);
    }
    __syncthreads();

    #pragma unroll 2
    for (int i = 0; i < 16; i++) {
        const float4* zr = sz + i * 32 + hh * 16;
        float acc = 0.f;
        #pragma unroll
        for (int d4 = 0; d4 < 16; d4++) {
            float4 zv = zr[d4];
            acc += zv.x * wcol[d4 * 4 + 0];
            acc += zv.y * wcol[d4 * 4 + 1];
            acc += zv.z * wcol[d4 * 4 + 2];
            acc += zv.w * wcol[d4 * 4 + 3];
        }
        sp[i][t] = acc;
    }
    __syncthreads();

    #pragma unroll
    for (int rep = 0; rep < 8; rep++) {
        int o = rep * 128 + t;            // 0..1023
        int i = o >> 6, dpp = o & 63;
        int node = n0 + i;
        if (node < N) {
            int idx = node * DD + dpp;
            out[idx] = out[idx] + sp[i][dpp] + sp[i][64 + dpp] + bias[dpp];
        }
    }
}

// ---------------- launch ----------------------------------------------------
extern "C" void kernel_launch(void* const* d_in, const int* in_sizes, int n_in,
                              void* d_out, int out_size) {
    const float* x        = (const float*)d_in[0];
    const int*   ei       = (const int*)  d_in[1];
    const int*   eattr    = (const int*)  d_in[2];
    const float* W        = (const float*)d_in[3];
    const float* bW       = (const float*)d_in[4];
    const float* att      = (const float*)d_in[5];
    const float* bias     = (const float*)d_in[6];
    const float* bond_emb = (const float*)d_in[7];
    float* out = (float*)d_out;

    int N = in_sizes[0] / DD;
    int E = in_sizes[1] / 2;

    k_initprep<<<INIT_BLOCKS + 126, 256>>>(W, bW, att, bond_emb, N);
    k_adot_hist<<<(E + 255) / 256, 256>>>(x, ei, N, E);
    k_scan1<<<SCAN_BLOCKS, 1024>>>(N);
    k_scan3<<<SCAN_BLOCKS, 1024>>>(N);
    k_softperm<<<(E + 255) / 256, 256>>>(ei, eattr, E);
    k_sinv<<<(N * 2 + 255) / 256, 256>>>(N);
    k_aggr<<<888, 256>>>(x, out, N);
    k_zgemm<<<(N + 15) / 16, 128>>>(W, bias, out, N);
}

// round 11
// speedup vs baseline: 1.0535x; 1.0069x over previous
#include <cuda_runtime.h>
#include <cuda_fp16.h>
#include <math.h>

// Problem-shape constants (N=50000, E=1600000, D=64, H=2)
#define NN 50000
#define EE 1600000
#define DD 64
#define HDIM 128   // H*D

#define SCAN_BLOCKS 49       // ceil(50000/1024)
#define INIT_BLOCKS 391      // ceil(50000*2/256)

// ---------------- scratch (device globals; no allocation allowed) ----------
__device__ float    g_adot_i[NN * 2];   // <h[n,h,:], att_i[h]>  (x-space dots)
__device__ float    g_adot_j[NN * 2];
__device__ float    g_s[NN * 2];        // segment sum of exp(alpha) over src
__device__ float    g_sinv[NN * 2];     // 0.5/(s+1e-16)
__device__ float    g_ebdot[30];        // <bond_emb[f,v,h,:], att_j[h]>
__device__ float    g_u[4 * DD];        // [ui_h0, ui_h1, uj_h0, uj_h1] 64-vecs
__device__ float    g_c[4];             // ci0, ci1, cj0, cj1 (bW dot att)
__device__ unsigned g_bsumh[125 * DD];  // half2 per (code,d): (bond'[h0,d], bond'[h1,d])
__device__ int      g_cnt[NN];          // in-degree (by col/dst)
__device__ int      g_base[NN];         // exclusive scan
__device__ int      g_cursor[NN];       // atomic cursors
__device__ int      g_part[64];         // scan partials
__device__ float4   g_rec[EE];          // sorted-by-dst: {row|code<<17, e0, e1, 0}
__device__ float    g_z[NN * HDIM];     // weighted x sums  [n][h*64+d]

__device__ __forceinline__ void red_add_v2(float* p, float a, float b) {
    asm volatile("red.global.add.v2.f32 [%0], {%1,%2};"
                 :: "l"(p), "f"(a), "f"(b) : "memory");
}

// ---------------- K0: init (zero s/cnt) + precompute tables, fused ---------
__global__ void k_initprep(const float* __restrict__ W, const float* __restrict__ bW,
                           const float* __restrict__ att, const float* __restrict__ bond_emb,
                           int N) {
    int bid = blockIdx.x;
    int t = threadIdx.x;
    if (bid < INIT_BLOCKS) {            // zero s / cnt
        int i = bid * 256 + t;
        if (i < N * 2) g_s[i] = 0.0f;
        if (i < N) g_cnt[i] = 0;
        return;
    }
    bid -= INIT_BLOCKS;                 // 0..125
    if (bid < 125) {
        if (t < DD) {   // d = t; pack (h0,h1) halves + fold bW
            int a0 = bid / 25, a1 = (bid / 5) % 5, a2 = bid % 5;
            float v0 = bond_emb[(0 * 5 + a0) * HDIM + t]
                     + bond_emb[(1 * 5 + a1) * HDIM + t]
                     + bond_emb[(2 * 5 + a2) * HDIM + t] + bW[t];
            float v1 = bond_emb[(0 * 5 + a0) * HDIM + DD + t]
                     + bond_emb[(1 * 5 + a1) * HDIM + DD + t]
                     + bond_emb[(2 * 5 + a2) * HDIM + DD + t] + bW[DD + t];
            __half2 hv = __float22half2_rn(make_float2(v0, v1));
            g_bsumh[bid * DD + t] = *reinterpret_cast<unsigned*>(&hv);
        }
        return;
    }
    // last block: u vectors, ebdot, c consts
    if (t < 128) {       // u vectors: (hh, d)
        int hh = t >> 6, d = t & 63;
        const float* wr = W + d * HDIM + hh * DD;
        const float* ai = att + hh * HDIM;
        const float* aj = att + hh * HDIM + DD;
        float ui = 0.f, uj = 0.f;
        #pragma unroll 8
        for (int k = 0; k < DD; k++) { ui += wr[k] * ai[k]; uj += wr[k] * aj[k]; }
        g_u[hh * DD + d] = ui;
        g_u[128 + hh * DD + d] = uj;
    } else if (t < 158) {  // ebdot
        int idx = t - 128;
        int f = idx / 10, v = (idx / 2) % 5, hh = idx & 1;
        const float* emb = bond_emb + (f * 5 + v) * HDIM + hh * DD;
        const float* aj  = att + hh * HDIM + DD;
        float acc = 0.0f;
        #pragma unroll 8
        for (int d = 0; d < DD; d++) acc += emb[d] * aj[d];
        g_ebdot[idx] = acc;
    } else if (t == 158) { // bW consts
        for (int hh = 0; hh < 2; hh++) {
            float ci = 0.f, cj = 0.f;
            for (int d = 0; d < DD; d++) {
                float b = bW[hh * DD + d];
                ci += b * att[hh * HDIM + d];
                cj += b * att[hh * HDIM + DD + d];
            }
            g_c[hh] = ci;
            g_c[2 + hh] = cj;
        }
    }
}

// ---------------- K1: per-node attention dots (x-space) + dst histogram ----
__global__ void __launch_bounds__(256) k_adot_hist(const float* __restrict__ x,
                                                   const int* __restrict__ ei,
                                                   int N, int E) {
    __shared__ float su[256];
    int t = threadIdx.x;
    su[t] = g_u[t];
    __syncthreads();

    int e = blockIdx.x * 256 + t;
    if (e < E) atomicAdd(&g_cnt[ei[E + e]], 1);

    int lane = t & 31;
    int n = blockIdx.x * 8 + (t >> 5);
    if (n >= N) return;
    float2 xv = reinterpret_cast<const float2*>(x)[n * 32 + lane];  // d=2lane,2lane+1
    float ai0 = xv.x * su[2 * lane]          + xv.y * su[2 * lane + 1];
    float ai1 = xv.x * su[64 + 2 * lane]     + xv.y * su[64 + 2 * lane + 1];
    float aj0 = xv.x * su[128 + 2 * lane]    + xv.y * su[128 + 2 * lane + 1];
    float aj1 = xv.x * su[192 + 2 * lane]    + xv.y * su[192 + 2 * lane + 1];
    #pragma unroll
    for (int o = 16; o > 0; o >>= 1) {
        ai0 += __shfl_down_sync(0xffffffffu, ai0, o);
        ai1 += __shfl_down_sync(0xffffffffu, ai1, o);
        aj0 += __shfl_down_sync(0xffffffffu, aj0, o);
        aj1 += __shfl_down_sync(0xffffffffu, aj1, o);
    }
    if (lane == 0) {
        reinterpret_cast<float2*>(g_adot_i)[n] = make_float2(ai0 + g_c[0], ai1 + g_c[1]);
        reinterpret_cast<float2*>(g_adot_j)[n] = make_float2(aj0 + g_c[2], aj1 + g_c[3]);
    }
}

// ---------------- K2: scan phase 1: per-block sums (coalesced) --------------
__global__ void __launch_bounds__(1024) k_scan1(int N) {
    __shared__ int sred[32];
    int t = threadIdx.x;
    int i = blockIdx.x * 1024 + t;
    int v = (i < N) ? g_cnt[i] : 0;
    int s = v;
    #pragma unroll
    for (int o = 16; o > 0; o >>= 1) s += __shfl_down_sync(0xffffffffu, s, o);
    if ((t & 31) == 0) sred[t >> 5] = s;
    __syncthreads();
    if (t < 32) {
        int r = sred[t];
        #pragma unroll
        for (int o = 16; o > 0; o >>= 1) r += __shfl_down_sync(0xffffffffu, r, o);
        if (t == 0) g_part[blockIdx.x] = r;
    }
}

// ---------------- K3: scan phase 2: per-block scan + local offset ----------
__global__ void __launch_bounds__(1024) k_scan3(int N) {
    __shared__ int ss[1024];
    __shared__ int soff;
    int t = threadIdx.x;
    int bid = blockIdx.x;
    if (t < 32) {
        int v = 0;
        if (t < bid) v += g_part[t];
        if (t + 32 < bid && t + 32 < SCAN_BLOCKS) v += g_part[t + 32];
        #pragma unroll
        for (int o = 16; o > 0; o >>= 1) v += __shfl_down_sync(0xffffffffu, v, o);
        if (t == 0) soff = v;
    }
    int i = bid * 1024 + t;
    int v = (i < N) ? g_cnt[i] : 0;
    ss[t] = v;
    __syncthreads();
    #pragma unroll
    for (int off = 1; off < 1024; off <<= 1) {
        int u = (t >= off) ? ss[t - off] : 0;
        __syncthreads();
        ss[t] += u;
        __syncthreads();
    }
    if (i < N) {
        int excl = ss[t] - v + soff;
        g_base[i] = excl;
        g_cursor[i] = excl;
    }
}

// ---------------- K4: fused logits+leakyrelu+exp+segsum+perm ---------------
__global__ void k_softperm(const int* __restrict__ ei, const int* __restrict__ eattr, int E) {
    __shared__ float seb[30];
    if (threadIdx.x < 30) seb[threadIdx.x] = g_ebdot[threadIdx.x];
    __syncthreads();
    int e = blockIdx.x * blockDim.x + threadIdx.x;
    if (e >= E) return;
    int row = ei[e];
    int col = ei[E + e];
    int a0 = eattr[e * 3 + 0], a1 = eattr[e * 3 + 1], a2 = eattr[e * 3 + 2];
    float2 di = reinterpret_cast<const float2*>(g_adot_i)[col];
    float2 dj = reinterpret_cast<const float2*>(g_adot_j)[row];
    float al0 = di.x + dj.x + seb[a0 * 2]     + seb[10 + a1 * 2]     + seb[20 + a2 * 2];
    float al1 = di.y + dj.y + seb[a0 * 2 + 1] + seb[10 + a1 * 2 + 1] + seb[20 + a2 * 2 + 1];
    al0 = (al0 >= 0.f) ? al0 : 0.2f * al0;
    al1 = (al1 >= 0.f) ? al1 : 0.2f * al1;
    float e0 = __expf(al0);
    float e1 = __expf(al1);
    red_add_v2(&g_s[row * 2], e0, e1);
    int code = a0 * 25 + a1 * 5 + a2;
    int packed = row | (code << 17);
    int pos = atomicAdd(&g_cursor[col], 1);
    g_rec[pos] = make_float4(__int_as_float(packed), e0, e1, 0.f);
}

// ---------------- K5: sinv = 0.5/(s+eps) ------------------------------------
__global__ void k_sinv(int N) {
    int i = blockIdx.x * blockDim.x + threadIdx.x;
    if (i < N * 2) g_sinv[i] = __fdividef(0.5f, g_s[i] + 1e-16f);
}

// ---------------- K6: per-dst aggregation of x (no atomics) -----------------
// Warp per dst node; HALF-WARP per edge with float4 lanes (j=lane&15 owns dims
// 4j..4j+3). Records staged in smem and consumed via LDS.128 broadcast (no
// shfl). Halves accumulate alternating edges; combined via shfl_xor(16) at
// node end. Per-edge LSU ops: 0.5 LDG.128(x) + 0.5 LDS.128(bond) + 0.5
// LDS.128(record) vs previous ~3.
#define AGGR_PAIR(KK)                                                              \
    {                                                                              \
        float4 rr = st[warp][2 * (KK) + sub];                                      \
        int pk = __float_as_int(rr.x);                                             \
        float w0 = rr.y, w1 = rr.z;                                                \
        int row = pk & 0x1FFFF;                                                    \
        int code = pk >> 17;                                                       \
        float4 xv = __ldg(reinterpret_cast<const float4*>(x) + row * 16 + j);      \
        uint4 u = *reinterpret_cast<const uint4*>(&sb[code * DD + 4 * j]);         \
        float2 f0 = __half22float2(*reinterpret_cast<__half2*>(&u.x));             \
        float2 f1 = __half22float2(*reinterpret_cast<__half2*>(&u.y));             \
        float2 f2 = __half22float2(*reinterpret_cast<__half2*>(&u.z));             \
        float2 f3 = __half22float2(*reinterpret_cast<__half2*>(&u.w));             \
        z0.x += w0 * xv.x; z0.y += w0 * xv.y; z0.z += w0 * xv.z; z0.w += w0 * xv.w;\
        z1.x += w1 * xv.x; z1.y += w1 * xv.y; z1.z += w1 * xv.z; z1.w += w1 * xv.w;\
        bb.x += w0 * f0.x + w1 * f0.y;                                             \
        bb.y += w0 * f1.x + w1 * f1.y;                                             \
        bb.z += w0 * f2.x + w1 * f2.y;                                             \
        bb.w += w0 * f3.x + w1 * f3.y;                                             \
    }

__global__ void __launch_bounds__(256) k_aggr(const float* __restrict__ x,
                                              float* __restrict__ out, int N) {
    __shared__ unsigned sb[125 * DD];   // 32000 B
    __shared__ float4 st[8][32];        // record staging, 4096 B
    int t = threadIdx.x;
    for (int i = t; i < 125 * DD; i += 256) sb[i] = g_bsumh[i];
    __syncthreads();

    int warp = t >> 5, lane = t & 31;
    int sub = lane >> 4;      // which edge of the pair
    int j = lane & 15;        // float4 lane (dims 4j..4j+3)
    int gw = blockIdx.x * 8 + warp;
    int nw = gridDim.x * 8;

    for (int n = gw; n < N; n += nw) {
        int beg = g_base[n];
        int deg = g_cnt[n];
        float4 z0 = make_float4(0.f, 0.f, 0.f, 0.f);
        float4 z1 = make_float4(0.f, 0.f, 0.f, 0.f);
        float4 bb = make_float4(0.f, 0.f, 0.f, 0.f);
        for (int k0 = 0; k0 < deg; k0 += 32) {
            int nb = min(32, deg - k0);
            float4 sv = make_float4(0.f, 0.f, 0.f, 0.f);   // w=0 padding is inert
            if (lane < nb) {
                float4 r = g_rec[beg + k0 + lane];
                int pk = __float_as_int(r.x);
                float2 si = reinterpret_cast<const float2*>(g_sinv)[pk & 0x1FFFF];
                sv = make_float4(r.x, r.y * si.x, r.z * si.y, 0.f);
            }
            st[warp][lane] = sv;
            __syncwarp();
            if (nb == 32) {
                #pragma unroll
                for (int k = 0; k < 16; k++) AGGR_PAIR(k)
            } else {
                int np = (nb + 1) >> 1;
                for (int k = 0; k < np; k++) AGGR_PAIR(k)
            }
            __syncwarp();
        }
        // combine the two half-warp partials (lanes j and j+16 own same dims)
        z0.x += __shfl_xor_sync(0xffffffffu, z0.x, 16);
        z0.y += __shfl_xor_sync(0xffffffffu, z0.y, 16);
        z0.z += __shfl_xor_sync(0xffffffffu, z0.z, 16);
        z0.w += __shfl_xor_sync(0xffffffffu, z0.w, 16);
        z1.x += __shfl_xor_sync(0xffffffffu, z1.x, 16);
        z1.y += __shfl_xor_sync(0xffffffffu, z1.y, 16);
        z1.z += __shfl_xor_sync(0xffffffffu, z1.z, 16);
        z1.w += __shfl_xor_sync(0xffffffffu, z1.w, 16);
        bb.x += __shfl_xor_sync(0xffffffffu, bb.x, 16);
        bb.y += __shfl_xor_sync(0xffffffffu, bb.y, 16);
        bb.z += __shfl_xor_sync(0xffffffffu, bb.z, 16);
        bb.w += __shfl_xor_sync(0xffffffffu, bb.w, 16);
        if (sub == 0) {
            float4* zp = reinterpret_cast<float4*>(g_z + n * HDIM);
            zp[j]      = z0;   // head0 dims 4j..4j+3
            zp[16 + j] = z1;   // head1
            reinterpret_cast<float4*>(out)[n * 16 + j] = bb;
        }
    }
}

// ---------------- K7: out += z @ W (head-structured) + bias ----------------
__global__ void __launch_bounds__(128) k_zgemm(const float* __restrict__ W,
                                               const float* __restrict__ bias,
                                               float* __restrict__ out, int N) {
    __shared__ float4 sz[16 * 32];      // 16 nodes x 128 floats
    __shared__ float sp[16][128];
    int t = threadIdx.x;
    int hh = t >> 6, dp = t & 63;
    float wcol[DD];
    #pragma unroll
    for (int d = 0; d < DD; d++) wcol[d] = W[d * HDIM + hh * DD + dp];

    int n0 = blockIdx.x * 16;
    for (int i = t; i < 16 * 32; i += 128) {
        int node = n0 + (i >> 5);
        sz[i] = (node < N) ? reinterpret_cast<const float4*>(g_z)[node * 32 + (i & 31)]
                           : make_float4(0.f, 0.f, 0.f, 0.f);
    }
    __syncthreads();

    #pragma unroll 2
    for (int i = 0; i < 16; i++) {
        const float4* zr = sz + i * 32 + hh * 16;
        float acc = 0.f;
        #pragma unroll
        for (int d4 = 0; d4 < 16; d4++) {
            float4 zv = zr[d4];
            acc += zv.x * wcol[d4 * 4 + 0];
            acc += zv.y * wcol[d4 * 4 + 1];
            acc += zv.z * wcol[d4 * 4 + 2];
            acc += zv.w * wcol[d4 * 4 + 3];
        }
        sp[i][t] = acc;
    }
    __syncthreads();

    #pragma unroll
    for (int rep = 0; rep < 8; rep++) {
        int o = rep * 128 + t;            // 0..1023
        int i = o >> 6, dpp = o & 63;
        int node = n0 + i;
        if (node < N) {
            int idx = node * DD + dpp;
            out[idx] = out[idx] + sp[i][dpp] + sp[i][64 + dpp] + bias[dpp];
        }
    }
}

// ---------------- launch ----------------------------------------------------
extern "C" void kernel_launch(void* const* d_in, const int* in_sizes, int n_in,
                              void* d_out, int out_size) {
    const float* x        = (const float*)d_in[0];
    const int*   ei       = (const int*)  d_in[1];
    const int*   eattr    = (const int*)  d_in[2];
    const float* W        = (const float*)d_in[3];
    const float* bW       = (const float*)d_in[4];
    const float* att      = (const float*)d_in[5];
    const float* bias     = (const float*)d_in[6];
    const float* bond_emb = (const float*)d_in[7];
    float* out = (float*)d_out;

    int N = in_sizes[0] / DD;
    int E = in_sizes[1] / 2;

    k_initprep<<<INIT_BLOCKS + 126, 256>>>(W, bW, att, bond_emb, N);
    k_adot_hist<<<(E + 255) / 256, 256>>>(x, ei, N, E);
    k_scan1<<<SCAN_BLOCKS, 1024>>>(N);
    k_scan3<<<SCAN_BLOCKS, 1024>>>(N);
    k_softperm<<<(E + 255) / 256, 256>>>(ei, eattr, E);
    k_sinv<<<(N * 2 + 255) / 256, 256>>>(N);
    k_aggr<<<888, 256>>>(x, out, N);
    k_zgemm<<<(N + 15) / 16, 128>>>(W, bias, out, N);
}

// round 12
// speedup vs baseline: 1.0631x; 1.0091x over previous
#include <cuda_runtime.h>
#include <cuda_fp16.h>
#include <math.h>

// Problem-shape constants (N=50000, E=1600000, D=64, H=2)
#define NN 50000
#define EE 1600000
#define DD 64
#define HDIM 128   // H*D

#define SCAN_BLOCKS 49       // ceil(50000/1024)
#define INIT_BLOCKS 391      // ceil(50000*2/256)

// ---------------- scratch (device globals; no allocation allowed) ----------
__device__ float    g_adot_i[NN * 2];   // <h[n,h,:], att_i[h]>  (x-space dots)
__device__ float    g_adot_j[NN * 2];
__device__ float    g_s[NN * 2];        // segment sum of exp(alpha) over src
__device__ float    g_sinv[NN * 2];     // 0.5/(s+1e-16)
__device__ float    g_ebdot[30];        // <bond_emb[f,v,h,:], att_j[h]>
__device__ float    g_u[4 * DD];        // [ui_h0, ui_h1, uj_h0, uj_h1] 64-vecs
__device__ float    g_c[4];             // ci0, ci1, cj0, cj1 (bW dot att)
__device__ unsigned g_bsumh[125 * DD];  // half2 per (code,d): (bond'[h0,d], bond'[h1,d])
__device__ unsigned g_xh[NN * 32];      // x in half2: [n][d/2], 6.4MB
__device__ int      g_cnt[NN];          // in-degree (by col/dst)
__device__ int      g_base[NN];         // exclusive scan
__device__ int      g_cursor[NN];       // atomic cursors
__device__ uint2    g_rec[EE];          // sorted-by-dst: {row|code<<17, half2(e0,e1)}
__device__ float    g_z[NN * HDIM];     // weighted x sums  [n][h*64+d]

__device__ __forceinline__ void red_add_v2(float* p, float a, float b) {
    asm volatile("red.global.add.v2.f32 [%0], {%1,%2};"
                 :: "l"(p), "f"(a), "f"(b) : "memory");
}

// ---------------- K0: init (zero s/cnt) + precompute tables, fused ---------
__global__ void k_initprep(const float* __restrict__ W, const float* __restrict__ bW,
                           const float* __restrict__ att, const float* __restrict__ bond_emb,
                           int N) {
    int bid = blockIdx.x;
    int t = threadIdx.x;
    if (bid < INIT_BLOCKS) {            // zero s / cnt
        int i = bid * 256 + t;
        if (i < N * 2) g_s[i] = 0.0f;
        if (i < N) g_cnt[i] = 0;
        return;
    }
    bid -= INIT_BLOCKS;                 // 0..125
    if (bid < 125) {
        if (t < DD) {   // d = t; pack (h0,h1) halves + fold bW
            int a0 = bid / 25, a1 = (bid / 5) % 5, a2 = bid % 5;
            float v0 = bond_emb[(0 * 5 + a0) * HDIM + t]
                     + bond_emb[(1 * 5 + a1) * HDIM + t]
                     + bond_emb[(2 * 5 + a2) * HDIM + t] + bW[t];
            float v1 = bond_emb[(0 * 5 + a0) * HDIM + DD + t]
                     + bond_emb[(1 * 5 + a1) * HDIM + DD + t]
                     + bond_emb[(2 * 5 + a2) * HDIM + DD + t] + bW[DD + t];
            __half2 hv = __float22half2_rn(make_float2(v0, v1));
            g_bsumh[bid * DD + t] = *reinterpret_cast<unsigned*>(&hv);
        }
        return;
    }
    // last block: u vectors, ebdot, c consts
    if (t < 128) {       // u vectors: (hh, d)
        int hh = t >> 6, d = t & 63;
        const float* wr = W + d * HDIM + hh * DD;
        const float* ai = att + hh * HDIM;
        const float* aj = att + hh * HDIM + DD;
        float ui = 0.f, uj = 0.f;
        #pragma unroll 8
        for (int k = 0; k < DD; k++) { ui += wr[k] * ai[k]; uj += wr[k] * aj[k]; }
        g_u[hh * DD + d] = ui;
        g_u[128 + hh * DD + d] = uj;
    } else if (t < 158) {  // ebdot
        int idx = t - 128;
        int f = idx / 10, v = (idx / 2) % 5, hh = idx & 1;
        const float* emb = bond_emb + (f * 5 + v) * HDIM + hh * DD;
        const float* aj  = att + hh * HDIM + DD;
        float acc = 0.0f;
        #pragma unroll 8
        for (int d = 0; d < DD; d++) acc += emb[d] * aj[d];
        g_ebdot[idx] = acc;
    } else if (t == 158) { // bW consts
        for (int hh = 0; hh < 2; hh++) {
            float ci = 0.f, cj = 0.f;
            for (int d = 0; d < DD; d++) {
                float b = bW[hh * DD + d];
                ci += b * att[hh * HDIM + d];
                cj += b * att[hh * HDIM + DD + d];
            }
            g_c[hh] = ci;
            g_c[2 + hh] = cj;
        }
    }
}

// ---------------- K1: per-node dots + dst histogram + half-x conversion ----
__global__ void __launch_bounds__(256) k_adot_hist(const float* __restrict__ x,
                                                   const int* __restrict__ ei,
                                                   int N, int E) {
    __shared__ float su[256];
    int t = threadIdx.x;
    su[t] = g_u[t];
    __syncthreads();

    int e = blockIdx.x * 256 + t;
    if (e < E) atomicAdd(&g_cnt[ei[E + e]], 1);

    int lane = t & 31;
    int n = blockIdx.x * 8 + (t >> 5);
    if (n >= N) return;
    float2 xv = reinterpret_cast<const float2*>(x)[n * 32 + lane];  // d=2lane,2lane+1
    // write half2-packed x (coalesced)
    {
        __half2 hv = __float22half2_rn(xv);
        g_xh[n * 32 + lane] = *reinterpret_cast<unsigned*>(&hv);
    }
    float ai0 = xv.x * su[2 * lane]          + xv.y * su[2 * lane + 1];
    float ai1 = xv.x * su[64 + 2 * lane]     + xv.y * su[64 + 2 * lane + 1];
    float aj0 = xv.x * su[128 + 2 * lane]    + xv.y * su[128 + 2 * lane + 1];
    float aj1 = xv.x * su[192 + 2 * lane]    + xv.y * su[192 + 2 * lane + 1];
    #pragma unroll
    for (int o = 16; o > 0; o >>= 1) {
        ai0 += __shfl_down_sync(0xffffffffu, ai0, o);
        ai1 += __shfl_down_sync(0xffffffffu, ai1, o);
        aj0 += __shfl_down_sync(0xffffffffu, aj0, o);
        aj1 += __shfl_down_sync(0xffffffffu, aj1, o);
    }
    if (lane == 0) {
        reinterpret_cast<float2*>(g_adot_i)[n] = make_float2(ai0 + g_c[0], ai1 + g_c[1]);
        reinterpret_cast<float2*>(g_adot_j)[n] = make_float2(aj0 + g_c[2], aj1 + g_c[3]);
    }
}

// ---------------- K2: fused scan (offset reduce + local block scan) ---------
// Block b: offset = sum cnt[0, b*1024) (coalesced strided reduce), then
// Hillis-Steele scan of its own 1024-chunk; writes base & cursor.
__global__ void __launch_bounds__(1024) k_scan(int N) {
    __shared__ int ss[1024];
    __shared__ int sred[32];
    __shared__ int soff;
    int t = threadIdx.x;
    int bid = blockIdx.x;

    // phase A: block offset
    int lim = bid << 10;
    int s = 0;
    for (int i = t; i < lim; i += 1024) s += g_cnt[i];
    #pragma unroll
    for (int o = 16; o > 0; o >>= 1) s += __shfl_down_sync(0xffffffffu, s, o);
    if ((t & 31) == 0) sred[t >> 5] = s;
    __syncthreads();
    if (t < 32) {
        int r = sred[t];
        #pragma unroll
        for (int o = 16; o > 0; o >>= 1) r += __shfl_down_sync(0xffffffffu, r, o);
        if (t == 0) soff = r;
    }

    // phase B: local inclusive scan
    int i = lim + t;
    int v = (i < N) ? g_cnt[i] : 0;
    ss[t] = v;
    __syncthreads();
    #pragma unroll
    for (int off = 1; off < 1024; off <<= 1) {
        int u = (t >= off) ? ss[t - off] : 0;
        __syncthreads();
        ss[t] += u;
        __syncthreads();
    }
    if (i < N) {
        int excl = ss[t] - v + soff;
        g_base[i] = excl;
        g_cursor[i] = excl;
    }
}

// ---------------- K3: fused logits+leakyrelu+exp+segsum+perm ---------------
__global__ void k_softperm(const int* __restrict__ ei, const int* __restrict__ eattr, int E) {
    __shared__ float seb[30];
    if (threadIdx.x < 30) seb[threadIdx.x] = g_ebdot[threadIdx.x];
    __syncthreads();
    int e = blockIdx.x * blockDim.x + threadIdx.x;
    if (e >= E) return;
    int row = ei[e];
    int col = ei[E + e];
    int a0 = eattr[e * 3 + 0], a1 = eattr[e * 3 + 1], a2 = eattr[e * 3 + 2];
    float2 di = reinterpret_cast<const float2*>(g_adot_i)[col];
    float2 dj = reinterpret_cast<const float2*>(g_adot_j)[row];
    float al0 = di.x + dj.x + seb[a0 * 2]     + seb[10 + a1 * 2]     + seb[20 + a2 * 2];
    float al1 = di.y + dj.y + seb[a0 * 2 + 1] + seb[10 + a1 * 2 + 1] + seb[20 + a2 * 2 + 1];
    al0 = (al0 >= 0.f) ? al0 : 0.2f * al0;
    al1 = (al1 >= 0.f) ? al1 : 0.2f * al1;
    float e0 = __expf(al0);
    float e1 = __expf(al1);
    red_add_v2(&g_s[row * 2], e0, e1);
    int code = a0 * 25 + a1 * 5 + a2;
    int packed = row | (code << 17);
    __half2 eh = __floats2half2_rn(e0, e1);
    int pos = atomicAdd(&g_cursor[col], 1);
    g_rec[pos] = make_uint2((unsigned)packed, *reinterpret_cast<unsigned*>(&eh));
}

// ---------------- K4: sinv = 0.5/(s+eps) ------------------------------------
__global__ void k_sinv(int N) {
    int i = blockIdx.x * blockDim.x + threadIdx.x;
    if (i < N * 2) g_sinv[i] = __fdividef(0.5f, g_s[i] + 1e-16f);
}

// ---------------- K5: per-dst aggregation of half-x (no atomics) ------------
// Warp per dst node; HALF-WARP per edge; lane j=lane&15 owns dims 4j..4j+3.
// x gathered as half2 pairs (LDG.64, 128B/row), records 8B, staged via smem.
#define AGGR_PAIR(KK)                                                              \
    {                                                                              \
        float4 rr = st[warp][2 * (KK) + sub];                                      \
        int pk = __float_as_int(rr.x);                                             \
        float w0 = rr.y, w1 = rr.z;                                                \
        int row = pk & 0x1FFFF;                                                    \
        int code = pk >> 17;                                                       \
        uint2 xu = __ldg(reinterpret_cast<const uint2*>(g_xh) + row * 16 + j);     \
        float2 xa = __half22float2(*reinterpret_cast<__half2*>(&xu.x));            \
        float2 xb = __half22float2(*reinterpret_cast<__half2*>(&xu.y));            \
        uint4 u = *reinterpret_cast<const uint4*>(&sb[code * DD + 4 * j]);         \
        float2 f0 = __half22float2(*reinterpret_cast<__half2*>(&u.x));             \
        float2 f1 = __half22float2(*reinterpret_cast<__half2*>(&u.y));             \
        float2 f2 = __half22float2(*reinterpret_cast<__half2*>(&u.z));             \
        float2 f3 = __half22float2(*reinterpret_cast<__half2*>(&u.w));             \
        z0.x += w0 * xa.x; z0.y += w0 * xa.y; z0.z += w0 * xb.x; z0.w += w0 * xb.y;\
        z1.x += w1 * xa.x; z1.y += w1 * xa.y; z1.z += w1 * xb.x; z1.w += w1 * xb.y;\
        bb.x += w0 * f0.x + w1 * f0.y;                                             \
        bb.y += w0 * f1.x + w1 * f1.y;                                             \
        bb.z += w0 * f2.x + w1 * f2.y;                                             \
        bb.w += w0 * f3.x + w1 * f3.y;                                             \
    }

__global__ void __launch_bounds__(256) k_aggr(float* __restrict__ out, int N) {
    __shared__ unsigned sb[125 * DD];   // 32000 B
    __shared__ float4 st[8][32];        // record staging, 4096 B
    int t = threadIdx.x;
    for (int i = t; i < 125 * DD; i += 256) sb[i] = g_bsumh[i];
    __syncthreads();

    int warp = t >> 5, lane = t & 31;
    int sub = lane >> 4;      // which edge of the pair
    int j = lane & 15;        // float4 lane (dims 4j..4j+3)
    int gw = blockIdx.x * 8 + warp;
    int nw = gridDim.x * 8;

    for (int n = gw; n < N; n += nw) {
        int beg = g_base[n];
        int deg = g_cnt[n];
        float4 z0 = make_float4(0.f, 0.f, 0.f, 0.f);
        float4 z1 = make_float4(0.f, 0.f, 0.f, 0.f);
        float4 bb = make_float4(0.f, 0.f, 0.f, 0.f);
        for (int k0 = 0; k0 < deg; k0 += 32) {
            int nb = min(32, deg - k0);
            float4 sv = make_float4(0.f, 0.f, 0.f, 0.f);   // w=0 padding is inert
            if (lane < nb) {
                uint2 r = g_rec[beg + k0 + lane];
                int pk = (int)r.x;
                float2 ee = __half22float2(*reinterpret_cast<__half2*>(&r.y));
                float2 si = reinterpret_cast<const float2*>(g_sinv)[pk & 0x1FFFF];
                sv = make_float4(__int_as_float(pk), ee.x * si.x, ee.y * si.y, 0.f);
            }
            st[warp][lane] = sv;
            __syncwarp();
            if (nb == 32) {
                #pragma unroll
                for (int k = 0; k < 16; k++) AGGR_PAIR(k)
            } else {
                int np = (nb + 1) >> 1;
                for (int k = 0; k < np; k++) AGGR_PAIR(k)
            }
            __syncwarp();
        }
        // combine the two half-warp partials (lanes j and j+16 own same dims)
        z0.x += __shfl_xor_sync(0xffffffffu, z0.x, 16);
        z0.y += __shfl_xor_sync(0xffffffffu, z0.y, 16);
        z0.z += __shfl_xor_sync(0xffffffffu, z0.z, 16);
        z0.w += __shfl_xor_sync(0xffffffffu, z0.w, 16);
        z1.x += __shfl_xor_sync(0xffffffffu, z1.x, 16);
        z1.y += __shfl_xor_sync(0xffffffffu, z1.y, 16);
        z1.z += __shfl_xor_sync(0xffffffffu, z1.z, 16);
        z1.w += __shfl_xor_sync(0xffffffffu, z1.w, 16);
        bb.x += __shfl_xor_sync(0xffffffffu, bb.x, 16);
        bb.y += __shfl_xor_sync(0xffffffffu, bb.y, 16);
        bb.z += __shfl_xor_sync(0xffffffffu, bb.z, 16);
        bb.w += __shfl_xor_sync(0xffffffffu, bb.w, 16);
        if (sub == 0) {
            float4* zp = reinterpret_cast<float4*>(g_z + n * HDIM);
            zp[j]      = z0;   // head0 dims 4j..4j+3
            zp[16 + j] = z1;   // head1
            reinterpret_cast<float4*>(out)[n * 16 + j] = bb;
        }
    }
}

// ---------------- K6: out += z @ W (head-structured) + bias ----------------
__global__ void __launch_bounds__(128) k_zgemm(const float* __restrict__ W,
                                               const float* __restrict__ bias,
                                               float* __restrict__ out, int N) {
    __shared__ float4 sz[16 * 32];      // 16 nodes x 128 floats
    __shared__ float sp[16][128];
    int t = threadIdx.x;
    int hh = t >> 6, dp = t & 63;
    float wcol[DD];
    #pragma unroll
    for (int d = 0; d < DD; d++) wcol[d] = W[d * HDIM + hh * DD + dp];

    int n0 = blockIdx.x * 16;
    for (int i = t; i < 16 * 32; i += 128) {
        int node = n0 + (i >> 5);
        sz[i] = (node < N) ? reinterpret_cast<const float4*>(g_z)[node * 32 + (i & 31)]
                           : make_float4(0.f, 0.f, 0.f, 0.f);
    }
    __syncthreads();

    #pragma unroll 2
    for (int i = 0; i < 16; i++) {
        const float4* zr = sz + i * 32 + hh * 16;
        float acc = 0.f;
        #pragma unroll
        for (int d4 = 0; d4 < 16; d4++) {
            float4 zv = zr[d4];
            acc += zv.x * wcol[d4 * 4 + 0];
            acc += zv.y * wcol[d4 * 4 + 1];
            acc += zv.z * wcol[d4 * 4 + 2];
            acc += zv.w * wcol[d4 * 4 + 3];
        }
        sp[i][t] = acc;
    }
    __syncthreads();

    #pragma unroll
    for (int rep = 0; rep < 8; rep++) {
        int o = rep * 128 + t;            // 0..1023
        int i = o >> 6, dpp = o & 63;
        int node = n0 + i;
        if (node < N) {
            int idx = node * DD + dpp;
            out[idx] = out[idx] + sp[i][dpp] + sp[i][64 + dpp] + bias[dpp];
        }
    }
}

// ---------------- launch ----------------------------------------------------
extern "C" void kernel_launch(void* const* d_in, const int* in_sizes, int n_in,
                              void* d_out, int out_size) {
    const float* x        = (const float*)d_in[0];
    const int*   ei       = (const int*)  d_in[1];
    const int*   eattr    = (const int*)  d_in[2];
    const float* W        = (const float*)d_in[3];
    const float* bW       = (const float*)d_in[4];
    const float* att      = (const float*)d_in[5];
    const float* bias     = (const float*)d_in[6];
    const float* bond_emb = (const float*)d_in[7];
    float* out = (float*)d_out;

    int N = in_sizes[0] / DD;
    int E = in_sizes[1] / 2;

    k_initprep<<<INIT_BLOCKS + 126, 256>>>(W, bW, att, bond_emb, N);
    k_adot_hist<<<(E + 255) / 256, 256>>>(x, ei, N, E);
    k_scan<<<SCAN_BLOCKS, 1024>>>(N);
    k_softperm<<<(E + 255) / 256, 256>>>(ei, eattr, E);
    k_sinv<<<(N * 2 + 255) / 256, 256>>>(N);
    k_aggr<<<888, 256>>>(out, N);
    k_zgemm<<<(N + 15) / 16, 128>>>(W, bias, out, N);
}

// round 13
// speedup vs baseline: 1.1858x; 1.1154x over previous
#include <cuda_runtime.h>
#include <cuda_fp16.h>
#include <math.h>

// Problem-shape constants (N=50000, E=1600000, D=64, H=2)
#define NN 50000
#define EE 1600000
#define DD 64
#define HDIM 128   // H*D

#define SCAN_BLOCKS 49       // ceil(50000/1024)
#define INIT_BLOCKS 391      // ceil(50000*2/256)

// ---------------- scratch (device globals; no allocation allowed) ----------
__device__ float    g_adot_i[NN * 2];   // <h[n,h,:], att_i[h]>  (x-space dots)
__device__ float    g_adot_j[NN * 2];
__device__ float    g_s[NN * 2];        // segment sum of exp(alpha) over src
__device__ float    g_sinv[NN * 2];     // 0.5/(s+1e-16)
__device__ float    g_ebdot[30];        // <bond_emb[f,v,h,:], att_j[h]>
__device__ float    g_u[4 * DD];        // [ui_h0, ui_h1, uj_h0, uj_h1] 64-vecs
__device__ float    g_c[4];             // ci0, ci1, cj0, cj1 (bW dot att)
__device__ unsigned g_bsumh[125 * DD];  // half2 per (code,d): (bond'[h0,d], bond'[h1,d])
__device__ unsigned g_xh[NN * 32];      // x in half2: [n][d/2], 6.4MB
__device__ int      g_cnt[NN];          // in-degree (by col/dst)
__device__ int      g_base[NN];         // exclusive scan
__device__ int      g_cursor[NN];       // atomic cursors
__device__ uint2    g_rec[EE];          // sorted-by-dst: {row|code<<17, half2(e0,e1)}
__device__ float    g_z[NN * HDIM];     // weighted x sums  [n][h*64+d]
__device__ float    g_zb[NN * DD];      // bond partial of out  [n][d]

__device__ __forceinline__ void red_add_v2(float* p, float a, float b) {
    asm volatile("red.global.add.v2.f32 [%0], {%1,%2};"
                 :: "l"(p), "f"(a), "f"(b) : "memory");
}

// ---------------- K0: init (zero s/cnt) + precompute tables, fused ---------
__global__ void k_initprep(const float* __restrict__ W, const float* __restrict__ bW,
                           const float* __restrict__ att, const float* __restrict__ bond_emb,
                           int N) {
    int bid = blockIdx.x;
    int t = threadIdx.x;
    if (bid < INIT_BLOCKS) {            // zero s / cnt
        int i = bid * 256 + t;
        if (i < N * 2) g_s[i] = 0.0f;
        if (i < N) g_cnt[i] = 0;
        return;
    }
    bid -= INIT_BLOCKS;                 // 0..125
    if (bid < 125) {
        if (t < DD) {   // d = t; pack (h0,h1) halves + fold bW
            int a0 = bid / 25, a1 = (bid / 5) % 5, a2 = bid % 5;
            float v0 = bond_emb[(0 * 5 + a0) * HDIM + t]
                     + bond_emb[(1 * 5 + a1) * HDIM + t]
                     + bond_emb[(2 * 5 + a2) * HDIM + t] + bW[t];
            float v1 = bond_emb[(0 * 5 + a0) * HDIM + DD + t]
                     + bond_emb[(1 * 5 + a1) * HDIM + DD + t]
                     + bond_emb[(2 * 5 + a2) * HDIM + DD + t] + bW[DD + t];
            __half2 hv = __float22half2_rn(make_float2(v0, v1));
            g_bsumh[bid * DD + t] = *reinterpret_cast<unsigned*>(&hv);
        }
        return;
    }
    // last block: u vectors, ebdot, c consts
    if (t < 128) {       // u vectors: (hh, d)
        int hh = t >> 6, d = t & 63;
        const float* wr = W + d * HDIM + hh * DD;
        const float* ai = att + hh * HDIM;
        const float* aj = att + hh * HDIM + DD;
        float ui = 0.f, uj = 0.f;
        #pragma unroll 8
        for (int k = 0; k < DD; k++) { ui += wr[k] * ai[k]; uj += wr[k] * aj[k]; }
        g_u[hh * DD + d] = ui;
        g_u[128 + hh * DD + d] = uj;
    } else if (t < 158) {  // ebdot
        int idx = t - 128;
        int f = idx / 10, v = (idx / 2) % 5, hh = idx & 1;
        const float* emb = bond_emb + (f * 5 + v) * HDIM + hh * DD;
        const float* aj  = att + hh * HDIM + DD;
        float acc = 0.0f;
        #pragma unroll 8
        for (int d = 0; d < DD; d++) acc += emb[d] * aj[d];
        g_ebdot[idx] = acc;
    } else if (t == 158) { // bW consts
        for (int hh = 0; hh < 2; hh++) {
            float ci = 0.f, cj = 0.f;
            for (int d = 0; d < DD; d++) {
                float b = bW[hh * DD + d];
                ci += b * att[hh * HDIM + d];
                cj += b * att[hh * HDIM + DD + d];
            }
            g_c[hh] = ci;
            g_c[2 + hh] = cj;
        }
    }
}

// ---------------- K1: per-node dots + dst histogram + half-x conversion ----
__global__ void __launch_bounds__(256) k_adot_hist(const float* __restrict__ x,
                                                   const int* __restrict__ ei,
                                                   int N, int E) {
    __shared__ float su[256];
    int t = threadIdx.x;
    su[t] = g_u[t];
    __syncthreads();

    int e = blockIdx.x * 256 + t;
    if (e < E) atomicAdd(&g_cnt[ei[E + e]], 1);

    int lane = t & 31;
    int n = blockIdx.x * 8 + (t >> 5);
    if (n >= N) return;
    float2 xv = reinterpret_cast<const float2*>(x)[n * 32 + lane];  // d=2lane,2lane+1
    {
        __half2 hv = __float22half2_rn(xv);
        g_xh[n * 32 + lane] = *reinterpret_cast<unsigned*>(&hv);
    }
    float ai0 = xv.x * su[2 * lane]          + xv.y * su[2 * lane + 1];
    float ai1 = xv.x * su[64 + 2 * lane]     + xv.y * su[64 + 2 * lane + 1];
    float aj0 = xv.x * su[128 + 2 * lane]    + xv.y * su[128 + 2 * lane + 1];
    float aj1 = xv.x * su[192 + 2 * lane]    + xv.y * su[192 + 2 * lane + 1];
    #pragma unroll
    for (int o = 16; o > 0; o >>= 1) {
        ai0 += __shfl_down_sync(0xffffffffu, ai0, o);
        ai1 += __shfl_down_sync(0xffffffffu, ai1, o);
        aj0 += __shfl_down_sync(0xffffffffu, aj0, o);
        aj1 += __shfl_down_sync(0xffffffffu, aj1, o);
    }
    if (lane == 0) {
        reinterpret_cast<float2*>(g_adot_i)[n] = make_float2(ai0 + g_c[0], ai1 + g_c[1]);
        reinterpret_cast<float2*>(g_adot_j)[n] = make_float2(aj0 + g_c[2], aj1 + g_c[3]);
    }
}

// ---------------- K2: fused scan (offset reduce + local block scan) ---------
__global__ void __launch_bounds__(1024) k_scan(int N) {
    __shared__ int ss[1024];
    __shared__ int sred[32];
    __shared__ int soff;
    int t = threadIdx.x;
    int bid = blockIdx.x;

    int lim = bid << 10;
    int s = 0;
    for (int i = t; i < lim; i += 1024) s += g_cnt[i];
    #pragma unroll
    for (int o = 16; o > 0; o >>= 1) s += __shfl_down_sync(0xffffffffu, s, o);
    if ((t & 31) == 0) sred[t >> 5] = s;
    __syncthreads();
    if (t < 32) {
        int r = sred[t];
        #pragma unroll
        for (int o = 16; o > 0; o >>= 1) r += __shfl_down_sync(0xffffffffu, r, o);
        if (t == 0) soff = r;
    }

    int i = lim + t;
    int v = (i < N) ? g_cnt[i] : 0;
    ss[t] = v;
    __syncthreads();
    #pragma unroll
    for (int off = 1; off < 1024; off <<= 1) {
        int u = (t >= off) ? ss[t - off] : 0;
        __syncthreads();
        ss[t] += u;
        __syncthreads();
    }
    if (i < N) {
        int excl = ss[t] - v + soff;
        g_base[i] = excl;
        g_cursor[i] = excl;
    }
}

// ---------------- K3: fused logits+leakyrelu+exp+segsum+perm ---------------
__global__ void k_softperm(const int* __restrict__ ei, const int* __restrict__ eattr, int E) {
    __shared__ float seb[30];
    if (threadIdx.x < 30) seb[threadIdx.x] = g_ebdot[threadIdx.x];
    __syncthreads();
    int e = blockIdx.x * blockDim.x + threadIdx.x;
    if (e >= E) return;
    int row = ei[e];
    int col = ei[E + e];
    int a0 = eattr[e * 3 + 0], a1 = eattr[e * 3 + 1], a2 = eattr[e * 3 + 2];
    float2 di = reinterpret_cast<const float2*>(g_adot_i)[col];
    float2 dj = reinterpret_cast<const float2*>(g_adot_j)[row];
    float al0 = di.x + dj.x + seb[a0 * 2]     + seb[10 + a1 * 2]     + seb[20 + a2 * 2];
    float al1 = di.y + dj.y + seb[a0 * 2 + 1] + seb[10 + a1 * 2 + 1] + seb[20 + a2 * 2 + 1];
    al0 = (al0 >= 0.f) ? al0 : 0.2f * al0;
    al1 = (al1 >= 0.f) ? al1 : 0.2f * al1;
    float e0 = __expf(al0);
    float e1 = __expf(al1);
    red_add_v2(&g_s[row * 2], e0, e1);
    int code = a0 * 25 + a1 * 5 + a2;
    int packed = row | (code << 17);
    __half2 eh = __floats2half2_rn(e0, e1);
    int pos = atomicAdd(&g_cursor[col], 1);
    g_rec[pos] = make_uint2((unsigned)packed, *reinterpret_cast<unsigned*>(&eh));
}

// ---------------- K4: sinv = 0.5/(s+eps) ------------------------------------
__global__ void k_sinv(int N) {
    int i = blockIdx.x * blockDim.x + threadIdx.x;
    if (i < N * 2) g_sinv[i] = __fdividef(0.5f, g_s[i] + 1e-16f);
}

// ---------------- K5: per-dst aggregation of half-x (no atomics) ------------
// Warp per dst node; HALF-WARP per edge; lane j=lane&15 owns dims 4j..4j+3.
// launch_bounds(256,4) caps regs at 64 -> 4 blocks/SM = 32 warps (was ~2
// blocks at high regs). Inner loop unrolled only 4x to keep live-load count
// (and regs) low while retaining MLP=4 per half-warp.
#define AGGR_PAIR(KK)                                                              \
    {                                                                              \
        float4 rr = st[warp][2 * (KK) + sub];                                      \
        int pk = __float_as_int(rr.x);                                             \
        float w0 = rr.y, w1 = rr.z;                                                \
        int row = pk & 0x1FFFF;                                                    \
        int code = pk >> 17;                                                       \
        uint2 xu = __ldg(reinterpret_cast<const uint2*>(g_xh) + row * 16 + j);     \
        float2 xa = __half22float2(*reinterpret_cast<__half2*>(&xu.x));            \
        float2 xb = __half22float2(*reinterpret_cast<__half2*>(&xu.y));            \
        uint4 u = *reinterpret_cast<const uint4*>(&sb[code * DD + 4 * j]);         \
        float2 f0 = __half22float2(*reinterpret_cast<__half2*>(&u.x));             \
        float2 f1 = __half22float2(*reinterpret_cast<__half2*>(&u.y));             \
        float2 f2 = __half22float2(*reinterpret_cast<__half2*>(&u.z));             \
        float2 f3 = __half22float2(*reinterpret_cast<__half2*>(&u.w));             \
        z0.x += w0 * xa.x; z0.y += w0 * xa.y; z0.z += w0 * xb.x; z0.w += w0 * xb.y;\
        z1.x += w1 * xa.x; z1.y += w1 * xa.y; z1.z += w1 * xb.x; z1.w += w1 * xb.y;\
        bb.x += w0 * f0.x + w1 * f0.y;                                             \
        bb.y += w0 * f1.x + w1 * f1.y;                                             \
        bb.z += w0 * f2.x + w1 * f2.y;                                             \
        bb.w += w0 * f3.x + w1 * f3.y;                                             \
    }

__global__ void __launch_bounds__(256, 4) k_aggr(int N) {
    __shared__ unsigned sb[125 * DD];   // 32000 B
    __shared__ float4 st[8][32];        // record staging, 4096 B
    int t = threadIdx.x;
    for (int i = t; i < 125 * DD; i += 256) sb[i] = g_bsumh[i];
    __syncthreads();

    int warp = t >> 5, lane = t & 31;
    int sub = lane >> 4;      // which edge of the pair
    int j = lane & 15;        // float4 lane (dims 4j..4j+3)
    int gw = blockIdx.x * 8 + warp;
    int nw = gridDim.x * 8;

    for (int n = gw; n < N; n += nw) {
        int beg = g_base[n];
        int deg = g_cnt[n];
        float4 z0 = make_float4(0.f, 0.f, 0.f, 0.f);
        float4 z1 = make_float4(0.f, 0.f, 0.f, 0.f);
        float4 bb = make_float4(0.f, 0.f, 0.f, 0.f);
        for (int k0 = 0; k0 < deg; k0 += 32) {
            int nb = min(32, deg - k0);
            float4 sv = make_float4(0.f, 0.f, 0.f, 0.f);   // w=0 padding is inert
            if (lane < nb) {
                uint2 r = g_rec[beg + k0 + lane];
                int pk = (int)r.x;
                float2 ee = __half22float2(*reinterpret_cast<__half2*>(&r.y));
                float2 si = reinterpret_cast<const float2*>(g_sinv)[pk & 0x1FFFF];
                sv = make_float4(__int_as_float(pk), ee.x * si.x, ee.y * si.y, 0.f);
            }
            st[warp][lane] = sv;
            __syncwarp();
            int np = (nb + 1) >> 1;
            #pragma unroll 4
            for (int k = 0; k < np; k++) AGGR_PAIR(k)
            __syncwarp();
        }
        // combine the two half-warp partials (lanes j and j+16 own same dims)
        z0.x += __shfl_xor_sync(0xffffffffu, z0.x, 16);
        z0.y += __shfl_xor_sync(0xffffffffu, z0.y, 16);
        z0.z += __shfl_xor_sync(0xffffffffu, z0.z, 16);
        z0.w += __shfl_xor_sync(0xffffffffu, z0.w, 16);
        z1.x += __shfl_xor_sync(0xffffffffu, z1.x, 16);
        z1.y += __shfl_xor_sync(0xffffffffu, z1.y, 16);
        z1.z += __shfl_xor_sync(0xffffffffu, z1.z, 16);
        z1.w += __shfl_xor_sync(0xffffffffu, z1.w, 16);
        bb.x += __shfl_xor_sync(0xffffffffu, bb.x, 16);
        bb.y += __shfl_xor_sync(0xffffffffu, bb.y, 16);
        bb.z += __shfl_xor_sync(0xffffffffu, bb.z, 16);
        bb.w += __shfl_xor_sync(0xffffffffu, bb.w, 16);
        if (sub == 0) {
            float4* zp = reinterpret_cast<float4*>(g_z + n * HDIM);
            zp[j]      = z0;   // head0 dims 4j..4j+3
            zp[16 + j] = z1;   // head1
            reinterpret_cast<float4*>(g_zb)[n * 16 + j] = bb;
        }
    }
}

// ---------------- K6: out = z @ W + zb + bias (single write, no RMW) --------
__global__ void __launch_bounds__(128) k_zgemm(const float* __restrict__ W,
                                               const float* __restrict__ bias,
                                               float* __restrict__ out, int N) {
    __shared__ float4 sz[16 * 32];      // 16 nodes x 128 floats
    __shared__ float sp[16][128];
    int t = threadIdx.x;
    int hh = t >> 6, dp = t & 63;
    float wcol[DD];
    #pragma unroll
    for (int d = 0; d < DD; d++) wcol[d] = W[d * HDIM + hh * DD + dp];

    int n0 = blockIdx.x * 16;
    for (int i = t; i < 16 * 32; i += 128) {
        int node = n0 + (i >> 5);
        sz[i] = (node < N) ? reinterpret_cast<const float4*>(g_z)[node * 32 + (i & 31)]
                           : make_float4(0.f, 0.f, 0.f, 0.f);
    }
    __syncthreads();

    #pragma unroll 2
    for (int i = 0; i < 16; i++) {
        const float4* zr = sz + i * 32 + hh * 16;
        float acc = 0.f;
        #pragma unroll
        for (int d4 = 0; d4 < 16; d4++) {
            float4 zv = zr[d4];
            acc += zv.x * wcol[d4 * 4 + 0];
            acc += zv.y * wcol[d4 * 4 + 1];
            acc += zv.z * wcol[d4 * 4 + 2];
            acc += zv.w * wcol[d4 * 4 + 3];
        }
        sp[i][t] = acc;
    }
    __syncthreads();

    #pragma unroll
    for (int rep = 0; rep < 8; rep++) {
        int o = rep * 128 + t;            // 0..1023
        int i = o >> 6, dpp = o & 63;
        int node = n0 + i;
        if (node < N) {
            int idx = node * DD + dpp;
            out[idx] = sp[i][dpp] + sp[i][64 + dpp] + g_zb[idx] + bias[dpp];
        }
    }
}

// ---------------- launch ----------------------------------------------------
extern "C" void kernel_launch(void* const* d_in, const int* in_sizes, int n_in,
                              void* d_out, int out_size) {
    const float* x        = (const float*)d_in[0];
    const int*   ei       = (const int*)  d_in[1];
    const int*   eattr    = (const int*)  d_in[2];
    const float* W        = (const float*)d_in[3];
    const float* bW       = (const float*)d_in[4];
    const float* att      = (const float*)d_in[5];
    const float* bias     = (const float*)d_in[6];
    const float* bond_emb = (const float*)d_in[7];
    float* out = (float*)d_out;

    int N = in_sizes[0] / DD;
    int E = in_sizes[1] / 2;

    k_initprep<<<INIT_BLOCKS + 126, 256>>>(W, bW, att, bond_emb, N);
    k_adot_hist<<<(E + 255) / 256, 256>>>(x, ei, N, E);
    k_scan<<<SCAN_BLOCKS, 1024>>>(N);
    k_softperm<<<(E + 255) / 256, 256>>>(ei, eattr, E);
    k_sinv<<<(N * 2 + 255) / 256, 256>>>(N);
    k_aggr<<<888, 256>>>(N);
    k_zgemm<<<(N + 15) / 16, 128>>>(W, bias, out, N);
}